// round 3
// baseline (speedup 1.0000x reference)
#include <cuda_runtime.h>
#include <cuda_bf16.h>
#include <math.h>

// ---------------------------------------------------------------------------
// Problem constants
// ---------------------------------------------------------------------------
#define BATCH 4
#define SEQ   1024
#define DIM   1024
#define NH    16
#define HS    64
#define NL    4
#define FFD   4096
#define VOCAB 32000
#define ROWS  (BATCH * SEQ)            // 4096 token rows

// ---------------------------------------------------------------------------
// Scratch (static device globals: allowed; runtime alloc is not)
// ---------------------------------------------------------------------------
__device__ float g_x   [(size_t)ROWS * DIM];          // residual stream
__device__ float g_h   [(size_t)ROWS * DIM];          // LN output
__device__ float g_qkv [(size_t)ROWS * 3 * DIM];      // [row][3*1024] q|k|v, head-major inside
__device__ float g_o   [(size_t)ROWS * DIM];          // attn output (b,t,h,s)
__device__ float g_ff  [(size_t)ROWS * FFD];          // MLP hidden
__device__ float g_wp  [(size_t)DIM * 3 * DIM];       // packed Wqkv for one layer
__device__ float g_log [(size_t)ROWS * VOCAB];        // logits (524 MB)
__device__ float g_rl  [ROWS];                        // per-row loss

// ---------------------------------------------------------------------------
// Embedding: x = tok_emb[idx] + pos_emb[t]
// ---------------------------------------------------------------------------
__global__ void embed_kernel(const int* __restrict__ idx,
                             const float* __restrict__ tok,
                             const float* __restrict__ pos,
                             float* __restrict__ x)
{
    int row = blockIdx.x;
    int t   = row & (SEQ - 1);
    int tk  = idx[row];
    const float* te = tok + (size_t)tk * DIM;
    const float* pe = pos + (size_t)t * DIM;
    float* xr = x + (size_t)row * DIM;
    for (int i = threadIdx.x; i < DIM; i += blockDim.x)
        xr[i] = te[i] + pe[i];
}

// ---------------------------------------------------------------------------
// LayerNorm (one block per row of 1024)
// ---------------------------------------------------------------------------
__global__ void ln_kernel(const float* __restrict__ x,
                          const float* __restrict__ g,
                          const float* __restrict__ b,
                          float* __restrict__ y)
{
    int row = blockIdx.x;
    int tid = threadIdx.x;
    const float* xr = x + (size_t)row * DIM;
    float* yr = y + (size_t)row * DIM;

    float s = 0.f, ss = 0.f;
    for (int i = tid; i < DIM; i += 256) {
        float v = xr[i];
        s += v; ss += v * v;
    }
    __shared__ float rs[256], rss[256];
    rs[tid] = s; rss[tid] = ss;
    __syncthreads();
    for (int st = 128; st > 0; st >>= 1) {
        if (tid < st) { rs[tid] += rs[tid + st]; rss[tid] += rss[tid + st]; }
        __syncthreads();
    }
    float mean = rs[0] * (1.0f / DIM);
    float var  = rss[0] * (1.0f / DIM) - mean * mean;
    var = fmaxf(var, 0.f);
    float rstd = rsqrtf(var + 1e-5f);
    for (int i = tid; i < DIM; i += 256)
        yr[i] = (xr[i] - mean) * rstd * g[i] + b[i];
}

// ---------------------------------------------------------------------------
// Pack Wq/Wk/Wv (L,H,D,HS) into [D][3*DIM] row-major for one layer
//   col 0..1023   = q (h*64+s), 1024..2047 = k, 2048..3071 = v
// ---------------------------------------------------------------------------
__global__ void pack_qkv_kernel(const float* __restrict__ Wq,
                                const float* __restrict__ Wk,
                                const float* __restrict__ Wv,
                                float* __restrict__ Wp, int l)
{
    int i = blockIdx.x * 256 + threadIdx.x;          // over DIM*3*DIM
    int d = i / (3 * DIM);
    int c = i % (3 * DIM);
    int which = c >> 10;
    int hc = c & 1023;
    int h = hc >> 6;
    int s = hc & 63;
    const float* W = (which == 0) ? Wq : (which == 1) ? Wk : Wv;
    Wp[i] = W[(((size_t)l * NH + h) * DIM + d) * HS + s];
}

// ---------------------------------------------------------------------------
// SGEMM 128x128x8, 8x8 per thread, 256 threads. Row-major A[MxK], B[KxN].
// EPI: 0 = C=acc+bias   1 = C=res+acc+bias   2 = C=relu(acc+bias)
// M,N multiples of 128; K multiple of 8.
// ---------------------------------------------------------------------------
template <int EPI>
__global__ __launch_bounds__(256)
void sgemm_kernel(const float* __restrict__ A, const float* __restrict__ B,
                  const float* __restrict__ bias, const float* __restrict__ res,
                  float* __restrict__ C, int M, int N, int K)
{
    __shared__ float As[8][128];
    __shared__ float Bs[8][128];
    const int tid = threadIdx.x;
    const int bm = blockIdx.y * 128;
    const int bn = blockIdx.x * 128;

    const int aRow = tid >> 1;
    const int aCol = (tid & 1) << 2;
    const int bRow = tid >> 5;
    const int bCol = (tid & 31) << 2;
    const int ty = (tid >> 4) << 3;
    const int tx = (tid & 15) << 3;

    float acc[8][8];
#pragma unroll
    for (int i = 0; i < 8; i++)
#pragma unroll
        for (int j = 0; j < 8; j++) acc[i][j] = 0.f;

    const float* Ap = A + (size_t)(bm + aRow) * K + aCol;
    const float* Bp = B + (size_t)bRow * N + bn + bCol;

    for (int k0 = 0; k0 < K; k0 += 8) {
        float4 a4 = *(const float4*)(Ap + k0);
        As[aCol + 0][aRow] = a4.x;
        As[aCol + 1][aRow] = a4.y;
        As[aCol + 2][aRow] = a4.z;
        As[aCol + 3][aRow] = a4.w;
        *(float4*)&Bs[bRow][bCol] = *(const float4*)(Bp + (size_t)k0 * N);
        __syncthreads();
#pragma unroll
        for (int k = 0; k < 8; k++) {
            float a[8], b[8];
            *(float4*)(a)     = *(float4*)&As[k][ty];
            *(float4*)(a + 4) = *(float4*)&As[k][ty + 4];
            *(float4*)(b)     = *(float4*)&Bs[k][tx];
            *(float4*)(b + 4) = *(float4*)&Bs[k][tx + 4];
#pragma unroll
            for (int i = 0; i < 8; i++)
#pragma unroll
                for (int j = 0; j < 8; j++)
                    acc[i][j] += a[i] * b[j];
        }
        __syncthreads();
    }

#pragma unroll
    for (int i = 0; i < 8; i++) {
        size_t row = (size_t)(bm + ty + i);
        float* Cr = C + row * N + bn + tx;
        const float* Rr = res ? (res + row * N + bn + tx) : nullptr;
#pragma unroll
        for (int j = 0; j < 8; j++) {
            float v = acc[i][j];
            if (bias) v += bias[bn + tx + j];
            if (EPI == 1) v += Rr[j];
            if (EPI == 2) v = fmaxf(v, 0.f);
            Cr[j] = v;
        }
    }
}

// ---------------------------------------------------------------------------
// Attention scores + causal softmax. One block per (q_row, b*h).
// Writes the [T] probability row (zeros beyond causal) into the attn output.
// ---------------------------------------------------------------------------
__global__ __launch_bounds__(256)
void attn_scores_kernel(const float* __restrict__ qkv, float* __restrict__ attn)
{
    int qt = blockIdx.x;
    int bh = blockIdx.y;            // b*NH + h
    int b  = bh >> 4;
    int hh = bh & 15;
    int tid = threadIdx.x;

    __shared__ float qs[HS];
    __shared__ float row[SEQ];
    __shared__ float red[256];

    const float* qrow = qkv + ((size_t)(b * SEQ + qt)) * (3 * DIM) + hh * HS;
    if (tid < HS) qs[tid] = qrow[tid];
    __syncthreads();

    float lmax = -INFINITY;
    for (int kt = tid; kt <= qt; kt += 256) {
        const float4* k4 = (const float4*)(qkv + ((size_t)(b * SEQ + kt)) * (3 * DIM) + DIM + hh * HS);
        float s = 0.f;
#pragma unroll
        for (int i = 0; i < 16; i++) {
            float4 kv = k4[i];
            s += qs[4 * i] * kv.x + qs[4 * i + 1] * kv.y
               + qs[4 * i + 2] * kv.z + qs[4 * i + 3] * kv.w;
        }
        s *= 0.125f;                 // HS^-0.5
        row[kt] = s;
        lmax = fmaxf(lmax, s);
    }
    red[tid] = lmax;
    __syncthreads();
    for (int st = 128; st > 0; st >>= 1) {
        if (tid < st) red[tid] = fmaxf(red[tid], red[tid + st]);
        __syncthreads();
    }
    float m = red[0];
    __syncthreads();

    float lsum = 0.f;
    for (int kt = tid; kt <= qt; kt += 256) {
        float e = expf(row[kt] - m);
        row[kt] = e;
        lsum += e;
    }
    red[tid] = lsum;
    __syncthreads();
    for (int st = 128; st > 0; st >>= 1) {
        if (tid < st) red[tid] += red[tid + st];
        __syncthreads();
    }
    float inv = 1.0f / red[0];

    float* dst = attn + ((size_t)bh * SEQ + qt) * SEQ;
    for (int kt = tid; kt < SEQ; kt += 256)
        dst[kt] = (kt <= qt) ? row[kt] * inv : 0.f;
}

// ---------------------------------------------------------------------------
// o[b,t,h,s] = sum_k wei[b,h,t,k] * v[b,h,k,s]. One block per (q_row, b*h).
// ---------------------------------------------------------------------------
__global__ __launch_bounds__(256)
void attn_av_kernel(const float* __restrict__ qkv, const float* __restrict__ attn,
                    float* __restrict__ o)
{
    int qt = blockIdx.x;
    int bh = blockIdx.y;
    int b  = bh >> 4;
    int hh = bh & 15;
    int tid = threadIdx.x;

    __shared__ float w[SEQ];
    __shared__ float part[4][HS];

    const float* wrow = attn + ((size_t)bh * SEQ + qt) * SEQ;
    for (int i = tid; i <= qt; i += 256) w[i] = wrow[i];
    __syncthreads();

    int s   = tid & 63;
    int grp = tid >> 6;
    float acc = 0.f;
    for (int kt = grp; kt <= qt; kt += 4)
        acc += w[kt] * qkv[((size_t)(b * SEQ + kt)) * (3 * DIM) + 2 * DIM + hh * HS + s];
    part[grp][s] = acc;
    __syncthreads();
    if (tid < HS) {
        float t = part[0][tid] + part[1][tid] + part[2][tid] + part[3][tid];
        o[((size_t)(b * SEQ + qt)) * DIM + hh * HS + tid] = t;
    }
}

// ---------------------------------------------------------------------------
// Per-row NLL with online logsumexp over vocab. One block per token row.
// ---------------------------------------------------------------------------
__global__ __launch_bounds__(256)
void loss_rows_kernel(const float* __restrict__ logits,
                      const int* __restrict__ targets,
                      float* __restrict__ rowloss)
{
    int row = blockIdx.x;
    int tid = threadIdx.x;
    const float* lr = logits + (size_t)row * VOCAB;

    float m = -INFINITY, s = 0.f;
    for (int v = tid; v < VOCAB; v += 256) {
        float z = lr[v];
        if (z > m) { s = s * expf(m - z) + 1.f; m = z; }
        else        s += expf(z - m);
    }
    __shared__ float ms[256], ss[256];
    ms[tid] = m; ss[tid] = s;
    __syncthreads();
    for (int st = 128; st > 0; st >>= 1) {
        if (tid < st) {
            float m2 = ms[tid + st], s2 = ss[tid + st];
            float M = fmaxf(ms[tid], m2);
            ss[tid] = ss[tid] * expf(ms[tid] - M) + s2 * expf(m2 - M);
            ms[tid] = M;
        }
        __syncthreads();
    }
    if (tid == 0) {
        float zt = lr[targets[row]];
        rowloss[row] = ms[0] + logf(ss[0]) - zt;
    }
}

__global__ void loss_reduce_kernel(const float* __restrict__ rowloss, float* __restrict__ out)
{
    __shared__ float red[256];
    int tid = threadIdx.x;
    float s = 0.f;
    for (int i = tid; i < ROWS; i += 256) s += rowloss[i];
    red[tid] = s;
    __syncthreads();
    for (int st = 128; st > 0; st >>= 1) {
        if (tid < st) red[tid] += red[tid + st];
        __syncthreads();
    }
    if (tid == 0) out[0] = red[0] * (1.0f / ROWS);
}

// ---------------------------------------------------------------------------
// Launch
// ---------------------------------------------------------------------------
extern "C" void kernel_launch(void* const* d_in, const int* in_sizes, int n_in,
                              void* d_out, int out_size)
{
    const int*   idx     = (const int*)  d_in[0];
    const int*   targets = (const int*)  d_in[1];
    const float* tok_emb = (const float*)d_in[2];
    const float* pos_emb = (const float*)d_in[3];
    const float* ln1_g   = (const float*)d_in[4];
    const float* ln1_b   = (const float*)d_in[5];
    const float* Wq      = (const float*)d_in[6];
    const float* Wk      = (const float*)d_in[7];
    const float* Wv      = (const float*)d_in[8];
    const float* Wp      = (const float*)d_in[9];
    const float* bp      = (const float*)d_in[10];
    const float* ln2_g   = (const float*)d_in[11];
    const float* ln2_b   = (const float*)d_in[12];
    const float* W1      = (const float*)d_in[13];
    const float* b1      = (const float*)d_in[14];
    const float* W2      = (const float*)d_in[15];
    const float* b2      = (const float*)d_in[16];
    const float* lnf_g   = (const float*)d_in[17];
    const float* lnf_b   = (const float*)d_in[18];
    const float* Wlm     = (const float*)d_in[19];
    const float* blm     = (const float*)d_in[20];

    float* out      = (float*)d_out;
    float* attn_out = out + 1;            // [L,B,H,T,T] after the scalar loss

    float *x, *h, *qkv, *o, *ff, *wp, *lg, *rl;
    cudaGetSymbolAddress((void**)&x,  g_x);
    cudaGetSymbolAddress((void**)&h,  g_h);
    cudaGetSymbolAddress((void**)&qkv,g_qkv);
    cudaGetSymbolAddress((void**)&o,  g_o);
    cudaGetSymbolAddress((void**)&ff, g_ff);
    cudaGetSymbolAddress((void**)&wp, g_wp);
    cudaGetSymbolAddress((void**)&lg, g_log);
    cudaGetSymbolAddress((void**)&rl, g_rl);

    embed_kernel<<<ROWS, 256>>>(idx, tok_emb, pos_emb, x);

    for (int l = 0; l < NL; l++) {
        // LN1
        ln_kernel<<<ROWS, 256>>>(x, ln1_g + (size_t)l * DIM, ln1_b + (size_t)l * DIM, h);
        // pack Wq|Wk|Wv into [D][3D]
        pack_qkv_kernel<<<(DIM * 3 * DIM) / 256, 256>>>(Wq, Wk, Wv, wp, l);
        // qkv = h @ Wpack
        sgemm_kernel<0><<<dim3(3 * DIM / 128, ROWS / 128), 256>>>(
            h, wp, nullptr, nullptr, qkv, ROWS, 3 * DIM, DIM);
        // scores + softmax -> attn output region (also the spec'd output)
        float* attnL = attn_out + (size_t)l * BATCH * NH * SEQ * SEQ;
        attn_scores_kernel<<<dim3(SEQ, BATCH * NH), 256>>>(qkv, attnL);
        // o = wei @ v
        attn_av_kernel<<<dim3(SEQ, BATCH * NH), 256>>>(qkv, attnL, o);
        // x = x + o @ Wp + bp
        sgemm_kernel<1><<<dim3(DIM / 128, ROWS / 128), 256>>>(
            o, Wp + (size_t)l * DIM * DIM, bp + (size_t)l * DIM, x, x, ROWS, DIM, DIM);
        // LN2
        ln_kernel<<<ROWS, 256>>>(x, ln2_g + (size_t)l * DIM, ln2_b + (size_t)l * DIM, h);
        // ff = relu(h @ W1 + b1)
        sgemm_kernel<2><<<dim3(FFD / 128, ROWS / 128), 256>>>(
            h, W1 + (size_t)l * DIM * FFD, b1 + (size_t)l * FFD, nullptr, ff, ROWS, FFD, DIM);
        // x = x + ff @ W2 + b2
        sgemm_kernel<1><<<dim3(DIM / 128, ROWS / 128), 256>>>(
            ff, W2 + (size_t)l * FFD * DIM, b2 + (size_t)l * DIM, x, x, ROWS, DIM, FFD);
    }

    // final LN + LM head
    ln_kernel<<<ROWS, 256>>>(x, lnf_g, lnf_b, h);
    sgemm_kernel<0><<<dim3(VOCAB / 128, ROWS / 128), 256>>>(
        h, Wlm, blm, nullptr, lg, ROWS, VOCAB, DIM);

    // loss
    loss_rows_kernel<<<ROWS, 256>>>(lg, targets, rl);
    loss_reduce_kernel<<<1, 256>>>(rl, out);
}

// round 5
// speedup vs baseline: 2.5047x; 2.5047x over previous
#include <cuda_runtime.h>
#include <cuda_bf16.h>
#include <math.h>
#include <stdint.h>

#define BATCH 4
#define SEQ   1024
#define DIM   1024
#define NH    16
#define HS    64
#define NL    4
#define FFD   4096
#define VOCAB 32000
#define ROWS  (BATCH * SEQ)

// ---------------------------------------------------------------------------
// Scratch
// ---------------------------------------------------------------------------
__device__ float g_x  [(size_t)ROWS * DIM];
__device__ float g_h  [(size_t)ROWS * DIM];
__device__ float g_qkv[(size_t)ROWS * 3 * DIM];
__device__ float g_o  [(size_t)ROWS * DIM];
__device__ float g_ff [(size_t)ROWS * FFD];
__device__ float g_wt [(size_t)VOCAB * DIM];     // transposed weights (reused)
__device__ float g_log[(size_t)ROWS * VOCAB];
__device__ float g_rl [ROWS];

// ---------------------------------------------------------------------------
// Helpers
// ---------------------------------------------------------------------------
__device__ __forceinline__ float tf32r(float x) {
    float y; asm("cvt.rna.tf32.f32 %0, %1;" : "=f"(y) : "f"(x)); return y;
}
__device__ __forceinline__ uint32_t s2u(const void* p) {
    uint32_t a;
    asm("{ .reg .u64 t; cvta.to.shared.u64 t, %1; cvt.u32.u64 %0, t; }" : "=r"(a) : "l"(p));
    return a;
}
__device__ __forceinline__ void cpa16(uint32_t dst, const float* src) {
    asm volatile("cp.async.cg.shared.global [%0], [%1], 16;" :: "r"(dst), "l"(src));
}

// ---------------------------------------------------------------------------
// Embedding
// ---------------------------------------------------------------------------
__global__ void embed_kernel(const int* __restrict__ idx,
                             const float* __restrict__ tok,
                             const float* __restrict__ pos,
                             float* __restrict__ x)
{
    int row = blockIdx.x;
    int t   = row & (SEQ - 1);
    int tk  = idx[row];
    const float* te = tok + (size_t)tk * DIM;
    const float* pe = pos + (size_t)t * DIM;
    float* xr = x + (size_t)row * DIM;
    for (int i = threadIdx.x; i < DIM; i += blockDim.x)
        xr[i] = te[i] + pe[i];
}

// ---------------------------------------------------------------------------
// LayerNorm (output tf32-rounded; it only feeds GEMMs)
// ---------------------------------------------------------------------------
__global__ void ln_kernel(const float* __restrict__ x,
                          const float* __restrict__ g,
                          const float* __restrict__ b,
                          float* __restrict__ y)
{
    int row = blockIdx.x;
    int tid = threadIdx.x;
    const float* xr = x + (size_t)row * DIM;
    float* yr = y + (size_t)row * DIM;

    float s = 0.f, ss = 0.f;
    for (int i = tid; i < DIM; i += 256) {
        float v = xr[i];
        s += v; ss += v * v;
    }
    __shared__ float rs[256], rss[256];
    rs[tid] = s; rss[tid] = ss;
    __syncthreads();
    for (int st = 128; st > 0; st >>= 1) {
        if (tid < st) { rs[tid] += rs[tid + st]; rss[tid] += rss[tid + st]; }
        __syncthreads();
    }
    float mean = rs[0] * (1.0f / DIM);
    float var  = rss[0] * (1.0f / DIM) - mean * mean;
    var = fmaxf(var, 0.f);
    float rstd = rsqrtf(var + 1e-5f);
    for (int i = tid; i < DIM; i += 256)
        yr[i] = tf32r((xr[i] - mean) * rstd * g[i] + b[i]);
}

// ---------------------------------------------------------------------------
// Pack Wq|Wk|Wv -> [3*DIM][DIM] K-major + tf32 round
// ---------------------------------------------------------------------------
__global__ void pack_qkv_t(const float* __restrict__ Wq,
                           const float* __restrict__ Wk,
                           const float* __restrict__ Wv,
                           float* __restrict__ out, int l)
{
    int c = blockIdx.x;                        // output row (N index), 0..3071
    int d = blockIdx.y * 256 + threadIdx.x;    // K index
    int which = c >> 10;
    int h = (c & 1023) >> 6;
    int s = c & 63;
    const float* W = (which == 0) ? Wq : (which == 1) ? Wk : Wv;
    out[(size_t)c * DIM + d] = tf32r(W[(((size_t)l * NH + h) * DIM + d) * HS + s]);
}

// ---------------------------------------------------------------------------
// Transpose [R][C] -> [C][R] + tf32 round
// ---------------------------------------------------------------------------
__global__ void transpose_k(const float* __restrict__ in, float* __restrict__ out,
                            int R, int C)
{
    __shared__ float t[32][33];
    int c0 = blockIdx.x * 32, r0 = blockIdx.y * 32;
    int x = threadIdx.x, y = threadIdx.y;
#pragma unroll
    for (int j = 0; j < 4; j++)
        t[y + 8 * j][x] = in[(size_t)(r0 + y + 8 * j) * C + c0 + x];
    __syncthreads();
#pragma unroll
    for (int j = 0; j < 4; j++)
        out[(size_t)(c0 + y + 8 * j) * R + r0 + x] = tf32r(t[x][y + 8 * j]);
}

// ---------------------------------------------------------------------------
// HMMA tf32 GEMM: C[M x N] = A[M x K] @ Bt[N x K]^T (+bias)(+res)(relu)
// 128x128 CTA tile, BK=32, 8 warps (64x32 warp tile), cp.async double buffer.
// EPI: 0 = +bias   1 = +bias+res   2 = relu(+bias) tf32-rounded
// ---------------------------------------------------------------------------
#define PAD 36
#define TILEB (128 * PAD * 4)
#define GEMM_SMEM (4 * TILEB)

template <int EPI>
__global__ __launch_bounds__(256, 2)
void gemm_mma(const float* __restrict__ A, const float* __restrict__ Bt,
              const float* __restrict__ bias, const float* __restrict__ res,
              float* __restrict__ C, int N, int K)
{
    extern __shared__ float smg[];
    uint32_t sA = s2u(smg);                 // As: [2][128][PAD]
    uint32_t sB = sA + 2 * TILEB;           // Bs: [2][128][PAD]
    float* Asf = smg;
    float* Bsf = smg + 2 * 128 * PAD;

    const int tid = threadIdx.x;
    const int bn = blockIdx.x * 128;
    const int bm = blockIdx.y * 128;
    const int wid = tid >> 5, l = tid & 31;
    const int wm = (wid & 1) * 64;          // warp row offset in tile
    const int wn = (wid >> 1) * 32;         // warp col offset in tile
    const int nt = K / 32;

    const int ldr = tid >> 3;               // load row base (0..31)
    const int ldc = (tid & 7) * 4;          // load col (0..28)
    const float* Ag = A  + (size_t)(bm + ldr) * K + ldc;
    const float* Bg = Bt + (size_t)(bn + ldr) * K + ldc;
    const uint32_t sAo = sA + (ldr * PAD + ldc) * 4;
    const uint32_t sBo = sB + (ldr * PAD + ldc) * 4;

    float acc[4][4][4];
#pragma unroll
    for (int i = 0; i < 4; i++)
#pragma unroll
        for (int j = 0; j < 4; j++)
#pragma unroll
            for (int c = 0; c < 4; c++) acc[i][j][c] = 0.f;

    // prologue: tile 0 -> buf 0
#pragma unroll
    for (int p = 0; p < 4; p++) {
        cpa16(sAo + p * 32 * PAD * 4, Ag + (size_t)(p * 32) * K);
        cpa16(sBo + p * 32 * PAD * 4, Bg + (size_t)(p * 32) * K);
    }
    asm volatile("cp.async.commit_group;" ::: "memory");

    for (int t = 0; t < nt; t++) {
        if (t + 1 < nt) {
            int buf = (t + 1) & 1;
            int ko = (t + 1) * 32;
#pragma unroll
            for (int p = 0; p < 4; p++) {
                cpa16(sAo + buf * TILEB + p * 32 * PAD * 4, Ag + (size_t)(p * 32) * K + ko);
                cpa16(sBo + buf * TILEB + p * 32 * PAD * 4, Bg + (size_t)(p * 32) * K + ko);
            }
            asm volatile("cp.async.commit_group;" ::: "memory");
            asm volatile("cp.async.wait_group 1;" ::: "memory");
        } else {
            asm volatile("cp.async.wait_group 0;" ::: "memory");
        }
        __syncthreads();

        const float* Ab = Asf + (t & 1) * 128 * PAD;
        const float* Bb = Bsf + (t & 1) * 128 * PAD;
#pragma unroll
        for (int kk = 0; kk < 4; kk++) {
            const int k0 = kk * 8;
            uint32_t a[4][4], b[4][2];
#pragma unroll
            for (int im = 0; im < 4; im++) {
                int r = wm + im * 16 + (l >> 2);
                a[im][0] = __float_as_uint(Ab[r * PAD + k0 + (l & 3)]);
                a[im][1] = __float_as_uint(Ab[(r + 8) * PAD + k0 + (l & 3)]);
                a[im][2] = __float_as_uint(Ab[r * PAD + k0 + (l & 3) + 4]);
                a[im][3] = __float_as_uint(Ab[(r + 8) * PAD + k0 + (l & 3) + 4]);
            }
#pragma unroll
            for (int in = 0; in < 4; in++) {
                int n = wn + in * 8 + (l >> 2);
                b[in][0] = __float_as_uint(Bb[n * PAD + k0 + (l & 3)]);
                b[in][1] = __float_as_uint(Bb[n * PAD + k0 + (l & 3) + 4]);
            }
#pragma unroll
            for (int im = 0; im < 4; im++)
#pragma unroll
                for (int in = 0; in < 4; in++) {
                    asm volatile(
                        "mma.sync.aligned.m16n8k8.row.col.f32.tf32.tf32.f32 "
                        "{%0,%1,%2,%3}, {%4,%5,%6,%7}, {%8,%9}, {%0,%1,%2,%3};"
                        : "+f"(acc[im][in][0]), "+f"(acc[im][in][1]),
                          "+f"(acc[im][in][2]), "+f"(acc[im][in][3])
                        : "r"(a[im][0]), "r"(a[im][1]), "r"(a[im][2]), "r"(a[im][3]),
                          "r"(b[in][0]), "r"(b[in][1]));
                }
        }
        __syncthreads();
    }

    // epilogue
#pragma unroll
    for (int im = 0; im < 4; im++) {
        int r0 = bm + wm + im * 16 + (l >> 2);
#pragma unroll
        for (int in = 0; in < 4; in++) {
            int cc = bn + wn + in * 8 + (l & 3) * 2;
            float b0 = 0.f, b1 = 0.f;
            if (bias) { b0 = bias[cc]; b1 = bias[cc + 1]; }
            float v0 = acc[im][in][0] + b0;
            float v1 = acc[im][in][1] + b1;
            float v2 = acc[im][in][2] + b0;
            float v3 = acc[im][in][3] + b1;
            if (EPI == 1) {
                v0 += res[(size_t)r0 * N + cc];
                v1 += res[(size_t)r0 * N + cc + 1];
                v2 += res[(size_t)(r0 + 8) * N + cc];
                v3 += res[(size_t)(r0 + 8) * N + cc + 1];
            }
            if (EPI == 2) {
                v0 = tf32r(fmaxf(v0, 0.f)); v1 = tf32r(fmaxf(v1, 0.f));
                v2 = tf32r(fmaxf(v2, 0.f)); v3 = tf32r(fmaxf(v3, 0.f));
            }
            float2 p0 = make_float2(v0, v1);
            float2 p1 = make_float2(v2, v3);
            *(float2*)&C[(size_t)r0 * N + cc] = p0;
            *(float2*)&C[(size_t)(r0 + 8) * N + cc] = p1;
        }
    }
}

// ---------------------------------------------------------------------------
// Fused attention: 8 q-rows per CTA. scores -> softmax (write attn) -> AV.
// ---------------------------------------------------------------------------
#define ATT_SMEM ((128 * 72 + 8 * 64 + 8 * 1024) * 4)

__global__ __launch_bounds__(256)
void attn_fused(const float* __restrict__ qkv, float* __restrict__ attn,
                float* __restrict__ o)
{
    extern __shared__ float smf[];
    float* Kt = smf;                 // [128][72] K tile (reused for V)
    float* qs = smf + 128 * 72;      // [8][64]
    float* rs = qs + 8 * 64;         // [8][1024]

    int q0 = blockIdx.x * 8;
    int bh = blockIdx.y;
    int b = bh >> 4, hh = bh & 15;
    int tid = threadIdx.x;
    int qmax = q0 + 7;
    int ntile = (qmax >> 7) + 1;
    int region = ntile << 7;

    for (int i = tid; i < 8 * 64; i += 256) {
        int r = i >> 6, c = i & 63;
        qs[i] = qkv[(size_t)(b * SEQ + q0 + r) * 3072 + hh * 64 + c];
    }

    // ---- scores ----
    int kt = tid & 127;
    int qb = tid >> 7;               // 0/1 -> rows qb, qb+2, qb+4, qb+6
    for (int t = 0; t < ntile; t++) {
        int kt0 = t << 7;
        __syncthreads();
#pragma unroll
        for (int u = 0; u < 8; u++) {
            int c = tid + 256 * u;
            int r = c >> 4, f4 = (c & 15) << 2;
            float4 v = *(const float4*)(qkv + (size_t)(b * SEQ + kt0 + r) * 3072 + 1024 + hh * 64 + f4);
            float* d = &Kt[r * 72 + f4];
            d[0] = v.x; d[1] = v.y; d[2] = v.z; d[3] = v.w;
        }
        __syncthreads();
        float a0 = 0.f, a1 = 0.f, a2 = 0.f, a3 = 0.f;
#pragma unroll
        for (int i4 = 0; i4 < 64; i4 += 4) {
            float4 kv = *(float4*)&Kt[kt * 72 + i4];
            float4 q4;
            q4 = *(const float4*)&qs[(qb + 0) * 64 + i4];
            a0 += q4.x * kv.x + q4.y * kv.y + q4.z * kv.z + q4.w * kv.w;
            q4 = *(const float4*)&qs[(qb + 2) * 64 + i4];
            a1 += q4.x * kv.x + q4.y * kv.y + q4.z * kv.z + q4.w * kv.w;
            q4 = *(const float4*)&qs[(qb + 4) * 64 + i4];
            a2 += q4.x * kv.x + q4.y * kv.y + q4.z * kv.z + q4.w * kv.w;
            q4 = *(const float4*)&qs[(qb + 6) * 64 + i4];
            a3 += q4.x * kv.x + q4.y * kv.y + q4.z * kv.z + q4.w * kv.w;
        }
        int ktg = kt0 + kt;
        rs[(qb + 0) * 1024 + ktg] = (ktg <= q0 + qb + 0) ? a0 * 0.125f : -INFINITY;
        rs[(qb + 2) * 1024 + ktg] = (ktg <= q0 + qb + 2) ? a1 * 0.125f : -INFINITY;
        rs[(qb + 4) * 1024 + ktg] = (ktg <= q0 + qb + 4) ? a2 * 0.125f : -INFINITY;
        rs[(qb + 6) * 1024 + ktg] = (ktg <= q0 + qb + 6) ? a3 * 0.125f : -INFINITY;
    }
    __syncthreads();

    // ---- softmax: warp w owns row w ----
    {
        int w = tid >> 5, lw = tid & 31;
        int qt = q0 + w;
        float m = -INFINITY;
        for (int j = lw; j <= qt; j += 32) m = fmaxf(m, rs[w * 1024 + j]);
#pragma unroll
        for (int st = 16; st > 0; st >>= 1)
            m = fmaxf(m, __shfl_xor_sync(0xFFFFFFFF, m, st));
        float ssum = 0.f;
        for (int j = lw; j <= qt; j += 32) {
            float e = __expf(rs[w * 1024 + j] - m);
            rs[w * 1024 + j] = e;
            ssum += e;
        }
#pragma unroll
        for (int st = 16; st > 0; st >>= 1)
            ssum += __shfl_xor_sync(0xFFFFFFFF, ssum, st);
        float inv = 1.0f / ssum;
        float* dst = attn + ((size_t)bh * SEQ + qt) * SEQ;
        for (int j = lw; j < region; j += 32) {
            float p = (j <= qt) ? rs[w * 1024 + j] * inv : 0.f;
            rs[w * 1024 + j] = p;
            dst[j] = p;
        }
        for (int j = region + lw; j < SEQ; j += 32) dst[j] = 0.f;
    }

    // ---- AV ----
    int s = tid & 63;
    int q2 = tid >> 6;
    float o0 = 0.f, o1 = 0.f;
    for (int t = 0; t < ntile; t++) {
        int kt0 = t << 7;
        __syncthreads();
#pragma unroll
        for (int u = 0; u < 8; u++) {
            int c = tid + 256 * u;
            int r = c >> 4, f4 = (c & 15) << 2;
            float4 v = *(const float4*)(qkv + (size_t)(b * SEQ + kt0 + r) * 3072 + 2048 + hh * 64 + f4);
            float* d = &Kt[r * 72 + f4];
            d[0] = v.x; d[1] = v.y; d[2] = v.z; d[3] = v.w;
        }
        __syncthreads();
#pragma unroll 4
        for (int k = 0; k < 128; k++) {
            float vv = Kt[k * 72 + s];
            o0 += rs[q2 * 1024 + kt0 + k] * vv;
            o1 += rs[(q2 + 4) * 1024 + kt0 + k] * vv;
        }
    }
    o[(size_t)(b * SEQ + q0 + q2) * DIM + hh * 64 + s] = tf32r(o0);
    o[(size_t)(b * SEQ + q0 + q2 + 4) * DIM + hh * 64 + s] = tf32r(o1);
}

// ---------------------------------------------------------------------------
// Loss
// ---------------------------------------------------------------------------
__global__ __launch_bounds__(256)
void loss_rows_kernel(const float* __restrict__ logits,
                      const int* __restrict__ targets,
                      float* __restrict__ rowloss)
{
    int row = blockIdx.x;
    int tid = threadIdx.x;
    const float* lr = logits + (size_t)row * VOCAB;

    float m = -INFINITY;
    for (int v = tid; v < VOCAB; v += 256) m = fmaxf(m, lr[v]);
    __shared__ float ms[256], ss[256];
    ms[tid] = m;
    __syncthreads();
    for (int st = 128; st > 0; st >>= 1) {
        if (tid < st) ms[tid] = fmaxf(ms[tid], ms[tid + st]);
        __syncthreads();
    }
    m = ms[0];
    float s = 0.f;
    for (int v = tid; v < VOCAB; v += 256) s += __expf(lr[v] - m);
    ss[tid] = s;
    __syncthreads();
    for (int st = 128; st > 0; st >>= 1) {
        if (tid < st) ss[tid] += ss[tid + st];
        __syncthreads();
    }
    if (tid == 0) {
        float zt = lr[targets[row]];
        rowloss[row] = m + logf(ss[0]) - zt;
    }
}

__global__ void loss_reduce_kernel(const float* __restrict__ rowloss, float* __restrict__ out)
{
    __shared__ float red[256];
    int tid = threadIdx.x;
    float s = 0.f;
    for (int i = tid; i < ROWS; i += 256) s += rowloss[i];
    red[tid] = s;
    __syncthreads();
    for (int st = 128; st > 0; st >>= 1) {
        if (tid < st) red[tid] += red[tid + st];
        __syncthreads();
    }
    if (tid == 0) out[0] = red[0] * (1.0f / ROWS);
}

// ---------------------------------------------------------------------------
// Host
// ---------------------------------------------------------------------------
extern "C" void kernel_launch(void* const* d_in, const int* in_sizes, int n_in,
                              void* d_out, int out_size)
{
    const int*   idx     = (const int*)  d_in[0];
    const int*   targets = (const int*)  d_in[1];
    const float* tok_emb = (const float*)d_in[2];
    const float* pos_emb = (const float*)d_in[3];
    const float* ln1_g   = (const float*)d_in[4];
    const float* ln1_b   = (const float*)d_in[5];
    const float* Wq      = (const float*)d_in[6];
    const float* Wk      = (const float*)d_in[7];
    const float* Wv      = (const float*)d_in[8];
    const float* Wp      = (const float*)d_in[9];
    const float* bp      = (const float*)d_in[10];
    const float* ln2_g   = (const float*)d_in[11];
    const float* ln2_b   = (const float*)d_in[12];
    const float* W1      = (const float*)d_in[13];
    const float* b1      = (const float*)d_in[14];
    const float* W2      = (const float*)d_in[15];
    const float* b2      = (const float*)d_in[16];
    const float* lnf_g   = (const float*)d_in[17];
    const float* lnf_b   = (const float*)d_in[18];
    const float* Wlm     = (const float*)d_in[19];
    const float* blm     = (const float*)d_in[20];

    float* out      = (float*)d_out;
    float* attn_out = out + 1;

    float *x, *h, *qkv, *o, *ff, *wt, *lg, *rl;
    cudaGetSymbolAddress((void**)&x,  g_x);
    cudaGetSymbolAddress((void**)&h,  g_h);
    cudaGetSymbolAddress((void**)&qkv,g_qkv);
    cudaGetSymbolAddress((void**)&o,  g_o);
    cudaGetSymbolAddress((void**)&ff, g_ff);
    cudaGetSymbolAddress((void**)&wt, g_wt);
    cudaGetSymbolAddress((void**)&lg, g_log);
    cudaGetSymbolAddress((void**)&rl, g_rl);

    cudaFuncSetAttribute(gemm_mma<0>, cudaFuncAttributeMaxDynamicSharedMemorySize, GEMM_SMEM);
    cudaFuncSetAttribute(gemm_mma<1>, cudaFuncAttributeMaxDynamicSharedMemorySize, GEMM_SMEM);
    cudaFuncSetAttribute(gemm_mma<2>, cudaFuncAttributeMaxDynamicSharedMemorySize, GEMM_SMEM);
    cudaFuncSetAttribute(attn_fused,  cudaFuncAttributeMaxDynamicSharedMemorySize, ATT_SMEM);

    embed_kernel<<<ROWS, 256>>>(idx, tok_emb, pos_emb, x);

    for (int l = 0; l < NL; l++) {
        ln_kernel<<<ROWS, 256>>>(x, ln1_g + (size_t)l * DIM, ln1_b + (size_t)l * DIM, h);
        pack_qkv_t<<<dim3(3 * DIM, DIM / 256), 256>>>(Wq, Wk, Wv, wt, l);
        gemm_mma<0><<<dim3(3 * DIM / 128, ROWS / 128), 256, GEMM_SMEM>>>(
            h, wt, nullptr, nullptr, qkv, 3 * DIM, DIM);

        float* attnL = attn_out + (size_t)l * BATCH * NH * SEQ * SEQ;
        attn_fused<<<dim3(SEQ / 8, BATCH * NH), 256, ATT_SMEM>>>(qkv, attnL, o);

        transpose_k<<<dim3(DIM / 32, DIM / 32), dim3(32, 8)>>>(
            Wp + (size_t)l * DIM * DIM, wt, DIM, DIM);
        gemm_mma<1><<<dim3(DIM / 128, ROWS / 128), 256, GEMM_SMEM>>>(
            o, wt, bp + (size_t)l * DIM, x, x, DIM, DIM);

        ln_kernel<<<ROWS, 256>>>(x, ln2_g + (size_t)l * DIM, ln2_b + (size_t)l * DIM, h);

        transpose_k<<<dim3(FFD / 32, DIM / 32), dim3(32, 8)>>>(
            W1 + (size_t)l * DIM * FFD, wt, DIM, FFD);
        gemm_mma<2><<<dim3(FFD / 128, ROWS / 128), 256, GEMM_SMEM>>>(
            h, wt, b1 + (size_t)l * FFD, nullptr, ff, FFD, DIM);

        transpose_k<<<dim3(DIM / 32, FFD / 32), dim3(32, 8)>>>(
            W2 + (size_t)l * FFD * DIM, wt, FFD, DIM);
        gemm_mma<1><<<dim3(DIM / 128, ROWS / 128), 256, GEMM_SMEM>>>(
            ff, wt, b2 + (size_t)l * DIM, x, x, DIM, FFD);
    }

    ln_kernel<<<ROWS, 256>>>(x, lnf_g, lnf_b, h);
    transpose_k<<<dim3(VOCAB / 32, DIM / 32), dim3(32, 8)>>>(Wlm, wt, DIM, VOCAB);
    gemm_mma<0><<<dim3(VOCAB / 128, ROWS / 128), 256, GEMM_SMEM>>>(
        h, wt, blm, nullptr, lg, VOCAB, DIM);

    loss_rows_kernel<<<ROWS, 256>>>(lg, targets, rl);
    loss_reduce_kernel<<<1, 256>>>(rl, out);
}

// round 6
// speedup vs baseline: 5.1273x; 2.0471x over previous
#include <cuda_runtime.h>
#include <cuda_fp16.h>
#include <math.h>
#include <stdint.h>

#define BATCH 4
#define SEQ   1024
#define DIM   1024
#define NH    16
#define HS    64
#define NL    4
#define FFD   4096
#define VOCAB 32000
#define ROWS  (BATCH * SEQ)

// ---------------------------------------------------------------------------
// Scratch
// ---------------------------------------------------------------------------
__device__ float  g_x  [(size_t)ROWS * DIM];        // residual (fp32)
__device__ __half g_hh [(size_t)ROWS * DIM];        // LN output (fp16)
__device__ float  g_qkv[(size_t)ROWS * 3 * DIM];    // q|k|v per row (fp32)
__device__ __half g_oh [(size_t)ROWS * DIM];        // attn output (fp16)
__device__ __half g_ffh[(size_t)ROWS * FFD];        // MLP hidden (fp16)
__device__ __half g_wth[(size_t)VOCAB * DIM];       // transposed weights (fp16)
__device__ float  g_log[(size_t)ROWS * VOCAB];      // logits
__device__ float  g_rl [ROWS];

// ---------------------------------------------------------------------------
// Helpers
// ---------------------------------------------------------------------------
__device__ __forceinline__ uint32_t s2u(const void* p) {
    uint32_t a;
    asm("{ .reg .u64 t; cvta.to.shared.u64 t, %1; cvt.u32.u64 %0, t; }" : "=r"(a) : "l"(p));
    return a;
}
__device__ __forceinline__ void cpa16(uint32_t dst, const void* src) {
    asm volatile("cp.async.cg.shared.global [%0], [%1], 16;" :: "r"(dst), "l"(src));
}

// ---------------------------------------------------------------------------
// Embedding
// ---------------------------------------------------------------------------
__global__ void embed_kernel(const int* __restrict__ idx,
                             const float* __restrict__ tok,
                             const float* __restrict__ pos,
                             float* __restrict__ x)
{
    int row = blockIdx.x;
    int t   = row & (SEQ - 1);
    int tk  = idx[row];
    const float* te = tok + (size_t)tk * DIM;
    const float* pe = pos + (size_t)t * DIM;
    float* xr = x + (size_t)row * DIM;
    for (int i = threadIdx.x; i < DIM; i += blockDim.x)
        xr[i] = te[i] + pe[i];
}

// ---------------------------------------------------------------------------
// LayerNorm -> fp16 (feeds GEMM A only)
// ---------------------------------------------------------------------------
__global__ void ln_kernel(const float* __restrict__ x,
                          const float* __restrict__ g,
                          const float* __restrict__ b,
                          __half* __restrict__ y)
{
    int row = blockIdx.x;
    int tid = threadIdx.x;
    const float* xr = x + (size_t)row * DIM;
    __half* yr = y + (size_t)row * DIM;

    float s = 0.f, ss = 0.f;
    for (int i = tid; i < DIM; i += 256) {
        float v = xr[i];
        s += v; ss += v * v;
    }
    __shared__ float rs[256], rss[256];
    rs[tid] = s; rss[tid] = ss;
    __syncthreads();
    for (int st = 128; st > 0; st >>= 1) {
        if (tid < st) { rs[tid] += rs[tid + st]; rss[tid] += rss[tid + st]; }
        __syncthreads();
    }
    float mean = rs[0] * (1.0f / DIM);
    float var  = rss[0] * (1.0f / DIM) - mean * mean;
    var = fmaxf(var, 0.f);
    float rstd = rsqrtf(var + 1e-5f);
    for (int i = tid; i < DIM; i += 256)
        yr[i] = __float2half((xr[i] - mean) * rstd * g[i] + b[i]);
}

// ---------------------------------------------------------------------------
// Pack Wq|Wk|Wv -> [3*DIM][DIM] K-major fp16
// ---------------------------------------------------------------------------
__global__ void pack_qkv_t(const float* __restrict__ Wq,
                           const float* __restrict__ Wk,
                           const float* __restrict__ Wv,
                           __half* __restrict__ out, int l)
{
    int c = blockIdx.x;                        // output row (N), 0..3071
    int d = blockIdx.y * 256 + threadIdx.x;    // K index
    int which = c >> 10;
    int h = (c & 1023) >> 6;
    int s = c & 63;
    const float* W = (which == 0) ? Wq : (which == 1) ? Wk : Wv;
    out[(size_t)c * DIM + d] = __float2half(W[(((size_t)l * NH + h) * DIM + d) * HS + s]);
}

// ---------------------------------------------------------------------------
// Transpose [R][C] fp32 -> [C][R] fp16
// ---------------------------------------------------------------------------
__global__ void transpose_k(const float* __restrict__ in, __half* __restrict__ out,
                            int R, int C)
{
    __shared__ float t[32][33];
    int c0 = blockIdx.x * 32, r0 = blockIdx.y * 32;
    int x = threadIdx.x, y = threadIdx.y;
#pragma unroll
    for (int j = 0; j < 4; j++)
        t[y + 8 * j][x] = in[(size_t)(r0 + y + 8 * j) * C + c0 + x];
    __syncthreads();
#pragma unroll
    for (int j = 0; j < 4; j++)
        out[(size_t)(c0 + y + 8 * j) * R + r0 + x] = __float2half(t[x][y + 8 * j]);
}

// ---------------------------------------------------------------------------
// fp16 HMMA GEMM: C[M x N] = A[M x K] @ Bt[N x K]^T (+bias)(+res)(relu)
// 128x128 CTA tile, BK=32, 8 warps (64x32 warp tiles), cp.async double buffer.
// EPI: 0 = fp32 C = acc+bias   1 = fp32 C = acc+bias+res   2 = fp16 C = relu
// ---------------------------------------------------------------------------
#define PAD 40                         // halves per smem row (conflict-free)
#define TILEB (128 * PAD * 2)          // bytes per operand tile buffer
#define GEMM_SMEM (4 * TILEB)          // 2 bufs x (A,B) = 40KB

template <int EPI>
__global__ __launch_bounds__(256, 2)
void gemm_mma(const __half* __restrict__ A, const __half* __restrict__ Bt,
              const float* __restrict__ bias, const float* __restrict__ res,
              void* __restrict__ Cv, int N, int K)
{
    extern __shared__ __half smh[];
    uint32_t sA = s2u(smh);
    uint32_t sB = sA + 2 * TILEB;
    __half* Asf = smh;
    __half* Bsf = smh + 2 * 128 * PAD;

    const int tid = threadIdx.x;
    const int bn = blockIdx.x * 128;
    const int bm = blockIdx.y * 128;
    const int wid = tid >> 5, l = tid & 31;
    const int wm = (wid & 1) * 64;
    const int wn = (wid >> 1) * 32;
    const int nt = K / 32;
    const int c2 = (l & 3) * 2;

    const int ldr = tid >> 2;              // 0..63
    const int ldc = (tid & 3) * 8;         // halves (16B chunks)
    const __half* Ag = A  + (size_t)(bm + ldr) * K + ldc;
    const __half* Bg = Bt + (size_t)(bn + ldr) * K + ldc;
    const uint32_t sAo = sA + (ldr * PAD + ldc) * 2;
    const uint32_t sBo = sB + (ldr * PAD + ldc) * 2;

    float acc[4][4][4];
#pragma unroll
    for (int i = 0; i < 4; i++)
#pragma unroll
        for (int j = 0; j < 4; j++)
#pragma unroll
            for (int c = 0; c < 4; c++) acc[i][j][c] = 0.f;

    // prologue: tile 0 -> buf 0 (rows ldr and ldr+64)
#pragma unroll
    for (int p = 0; p < 2; p++) {
        cpa16(sAo + p * 64 * PAD * 2, Ag + (size_t)(p * 64) * K);
        cpa16(sBo + p * 64 * PAD * 2, Bg + (size_t)(p * 64) * K);
    }
    asm volatile("cp.async.commit_group;" ::: "memory");

    for (int t = 0; t < nt; t++) {
        if (t + 1 < nt) {
            int buf = (t + 1) & 1;
            int ko = (t + 1) * 32;
#pragma unroll
            for (int p = 0; p < 2; p++) {
                cpa16(sAo + buf * TILEB + p * 64 * PAD * 2, Ag + (size_t)(p * 64) * K + ko);
                cpa16(sBo + buf * TILEB + p * 64 * PAD * 2, Bg + (size_t)(p * 64) * K + ko);
            }
            asm volatile("cp.async.commit_group;" ::: "memory");
            asm volatile("cp.async.wait_group 1;" ::: "memory");
        } else {
            asm volatile("cp.async.wait_group 0;" ::: "memory");
        }
        __syncthreads();

        const __half* Ab = Asf + (t & 1) * 128 * PAD;
        const __half* Bb = Bsf + (t & 1) * 128 * PAD;
#pragma unroll
        for (int kk = 0; kk < 2; kk++) {
            const int k0 = kk * 16;
            uint32_t a[4][4], b[4][2];
#pragma unroll
            for (int im = 0; im < 4; im++) {
                int r = wm + im * 16 + (l >> 2);
                a[im][0] = *(const uint32_t*)&Ab[r * PAD + k0 + c2];
                a[im][1] = *(const uint32_t*)&Ab[(r + 8) * PAD + k0 + c2];
                a[im][2] = *(const uint32_t*)&Ab[r * PAD + k0 + c2 + 8];
                a[im][3] = *(const uint32_t*)&Ab[(r + 8) * PAD + k0 + c2 + 8];
            }
#pragma unroll
            for (int in = 0; in < 4; in++) {
                int n = wn + in * 8 + (l >> 2);
                b[in][0] = *(const uint32_t*)&Bb[n * PAD + k0 + c2];
                b[in][1] = *(const uint32_t*)&Bb[n * PAD + k0 + c2 + 8];
            }
#pragma unroll
            for (int im = 0; im < 4; im++)
#pragma unroll
                for (int in = 0; in < 4; in++) {
                    asm volatile(
                        "mma.sync.aligned.m16n8k16.row.col.f32.f16.f16.f32 "
                        "{%0,%1,%2,%3}, {%4,%5,%6,%7}, {%8,%9}, {%0,%1,%2,%3};"
                        : "+f"(acc[im][in][0]), "+f"(acc[im][in][1]),
                          "+f"(acc[im][in][2]), "+f"(acc[im][in][3])
                        : "r"(a[im][0]), "r"(a[im][1]), "r"(a[im][2]), "r"(a[im][3]),
                          "r"(b[in][0]), "r"(b[in][1]));
                }
        }
        __syncthreads();
    }

    // epilogue
    float*  Cf = (float*)Cv;
    __half* Ch = (__half*)Cv;
#pragma unroll
    for (int im = 0; im < 4; im++) {
        int r0 = bm + wm + im * 16 + (l >> 2);
#pragma unroll
        for (int in = 0; in < 4; in++) {
            int cc = bn + wn + in * 8 + (l & 3) * 2;
            float b0 = 0.f, b1 = 0.f;
            if (bias) { b0 = bias[cc]; b1 = bias[cc + 1]; }
            float v0 = acc[im][in][0] + b0;
            float v1 = acc[im][in][1] + b1;
            float v2 = acc[im][in][2] + b0;
            float v3 = acc[im][in][3] + b1;
            if (EPI == 1) {
                v0 += res[(size_t)r0 * N + cc];
                v1 += res[(size_t)r0 * N + cc + 1];
                v2 += res[(size_t)(r0 + 8) * N + cc];
                v3 += res[(size_t)(r0 + 8) * N + cc + 1];
            }
            if (EPI == 2) {
                __half2 p0 = __halves2half2(__float2half(fmaxf(v0, 0.f)),
                                            __float2half(fmaxf(v1, 0.f)));
                __half2 p1 = __halves2half2(__float2half(fmaxf(v2, 0.f)),
                                            __float2half(fmaxf(v3, 0.f)));
                *(__half2*)&Ch[(size_t)r0 * N + cc] = p0;
                *(__half2*)&Ch[(size_t)(r0 + 8) * N + cc] = p1;
            } else {
                *(float2*)&Cf[(size_t)r0 * N + cc] = make_float2(v0, v1);
                *(float2*)&Cf[(size_t)(r0 + 8) * N + cc] = make_float2(v2, v3);
            }
        }
    }
}

// ---------------------------------------------------------------------------
// Fused attention: 8 q-rows per CTA. scores -> softmax (write attn) -> AV.
// ---------------------------------------------------------------------------
#define ATT_SMEM ((128 * 72 + 8 * 64 + 8 * 1024) * 4)

__global__ __launch_bounds__(256)
void attn_fused(const float* __restrict__ qkv, float* __restrict__ attn,
                __half* __restrict__ o)
{
    extern __shared__ float smf[];
    float* Kt = smf;                 // [128][72] K tile (reused for V)
    float* qs = smf + 128 * 72;      // [8][64]
    float* rs = qs + 8 * 64;         // [8][1024]

    int q0 = blockIdx.x * 8;
    int bh = blockIdx.y;
    int b = bh >> 4, hh = bh & 15;
    int tid = threadIdx.x;
    int qmax = q0 + 7;
    int ntile = (qmax >> 7) + 1;
    int region = ntile << 7;

    for (int i = tid; i < 8 * 64; i += 256) {
        int r = i >> 6, c = i & 63;
        qs[i] = qkv[(size_t)(b * SEQ + q0 + r) * 3072 + hh * 64 + c];
    }

    // ---- scores ----
    int kt = tid & 127;
    int qb = tid >> 7;               // 0/1 -> rows qb, qb+2, qb+4, qb+6
    for (int t = 0; t < ntile; t++) {
        int kt0 = t << 7;
        __syncthreads();
#pragma unroll
        for (int u = 0; u < 8; u++) {
            int c = tid + 256 * u;
            int r = c >> 4, f4 = (c & 15) << 2;
            float4 v = *(const float4*)(qkv + (size_t)(b * SEQ + kt0 + r) * 3072 + 1024 + hh * 64 + f4);
            float* d = &Kt[r * 72 + f4];
            d[0] = v.x; d[1] = v.y; d[2] = v.z; d[3] = v.w;
        }
        __syncthreads();
        float a0 = 0.f, a1 = 0.f, a2 = 0.f, a3 = 0.f;
#pragma unroll
        for (int i4 = 0; i4 < 64; i4 += 4) {
            float4 kv = *(float4*)&Kt[kt * 72 + i4];
            float4 q4;
            q4 = *(const float4*)&qs[(qb + 0) * 64 + i4];
            a0 += q4.x * kv.x + q4.y * kv.y + q4.z * kv.z + q4.w * kv.w;
            q4 = *(const float4*)&qs[(qb + 2) * 64 + i4];
            a1 += q4.x * kv.x + q4.y * kv.y + q4.z * kv.z + q4.w * kv.w;
            q4 = *(const float4*)&qs[(qb + 4) * 64 + i4];
            a2 += q4.x * kv.x + q4.y * kv.y + q4.z * kv.z + q4.w * kv.w;
            q4 = *(const float4*)&qs[(qb + 6) * 64 + i4];
            a3 += q4.x * kv.x + q4.y * kv.y + q4.z * kv.z + q4.w * kv.w;
        }
        int ktg = kt0 + kt;
        rs[(qb + 0) * 1024 + ktg] = (ktg <= q0 + qb + 0) ? a0 * 0.125f : -INFINITY;
        rs[(qb + 2) * 1024 + ktg] = (ktg <= q0 + qb + 2) ? a1 * 0.125f : -INFINITY;
        rs[(qb + 4) * 1024 + ktg] = (ktg <= q0 + qb + 4) ? a2 * 0.125f : -INFINITY;
        rs[(qb + 6) * 1024 + ktg] = (ktg <= q0 + qb + 6) ? a3 * 0.125f : -INFINITY;
    }
    __syncthreads();

    // ---- softmax: warp w owns row w ----
    {
        int w = tid >> 5, lw = tid & 31;
        int qt = q0 + w;
        float m = -INFINITY;
        for (int j = lw; j <= qt; j += 32) m = fmaxf(m, rs[w * 1024 + j]);
#pragma unroll
        for (int st = 16; st > 0; st >>= 1)
            m = fmaxf(m, __shfl_xor_sync(0xFFFFFFFF, m, st));
        float ssum = 0.f;
        for (int j = lw; j <= qt; j += 32) {
            float e = __expf(rs[w * 1024 + j] - m);
            rs[w * 1024 + j] = e;
            ssum += e;
        }
#pragma unroll
        for (int st = 16; st > 0; st >>= 1)
            ssum += __shfl_xor_sync(0xFFFFFFFF, ssum, st);
        float inv = 1.0f / ssum;
        float* dst = attn + ((size_t)bh * SEQ + qt) * SEQ;
        for (int j = lw; j < region; j += 32) {
            float p = (j <= qt) ? rs[w * 1024 + j] * inv : 0.f;
            rs[w * 1024 + j] = p;
            dst[j] = p;
        }
        for (int j = region + lw; j < SEQ; j += 32) dst[j] = 0.f;
    }

    // ---- AV ----
    int s = tid & 63;
    int q2 = tid >> 6;
    float o0 = 0.f, o1 = 0.f;
    for (int t = 0; t < ntile; t++) {
        int kt0 = t << 7;
        __syncthreads();
#pragma unroll
        for (int u = 0; u < 8; u++) {
            int c = tid + 256 * u;
            int r = c >> 4, f4 = (c & 15) << 2;
            float4 v = *(const float4*)(qkv + (size_t)(b * SEQ + kt0 + r) * 3072 + 2048 + hh * 64 + f4);
            float* d = &Kt[r * 72 + f4];
            d[0] = v.x; d[1] = v.y; d[2] = v.z; d[3] = v.w;
        }
        __syncthreads();
#pragma unroll 4
        for (int k = 0; k < 128; k++) {
            float vv = Kt[k * 72 + s];
            o0 += rs[q2 * 1024 + kt0 + k] * vv;
            o1 += rs[(q2 + 4) * 1024 + kt0 + k] * vv;
        }
    }
    o[(size_t)(b * SEQ + q0 + q2) * DIM + hh * 64 + s] = __float2half(o0);
    o[(size_t)(b * SEQ + q0 + q2 + 4) * DIM + hh * 64 + s] = __float2half(o1);
}

// ---------------------------------------------------------------------------
// Loss: single online logsumexp pass over vocab
// ---------------------------------------------------------------------------
__global__ __launch_bounds__(256)
void loss_rows_kernel(const float* __restrict__ logits,
                      const int* __restrict__ targets,
                      float* __restrict__ rowloss)
{
    int row = blockIdx.x;
    int tid = threadIdx.x;
    const float* lr = logits + (size_t)row * VOCAB;

    float m = -INFINITY, s = 0.f;
    for (int v = tid; v < VOCAB; v += 256) {
        float z = lr[v];
        if (z > m) { s = s * __expf(m - z) + 1.f; m = z; }
        else        s += __expf(z - m);
    }
    __shared__ float ms[256], ss[256];
    ms[tid] = m; ss[tid] = s;
    __syncthreads();
    for (int st = 128; st > 0; st >>= 1) {
        if (tid < st) {
            float m2 = ms[tid + st], s2 = ss[tid + st];
            float M = fmaxf(ms[tid], m2);
            ss[tid] = ss[tid] * __expf(ms[tid] - M) + s2 * __expf(m2 - M);
            ms[tid] = M;
        }
        __syncthreads();
    }
    if (tid == 0) {
        float zt = lr[targets[row]];
        rowloss[row] = ms[0] + logf(ss[0]) - zt;
    }
}

__global__ void loss_reduce_kernel(const float* __restrict__ rowloss, float* __restrict__ out)
{
    __shared__ float red[256];
    int tid = threadIdx.x;
    float s = 0.f;
    for (int i = tid; i < ROWS; i += 256) s += rowloss[i];
    red[tid] = s;
    __syncthreads();
    for (int st = 128; st > 0; st >>= 1) {
        if (tid < st) red[tid] += red[tid + st];
        __syncthreads();
    }
    if (tid == 0) out[0] = red[0] * (1.0f / ROWS);
}

// ---------------------------------------------------------------------------
// Host
// ---------------------------------------------------------------------------
extern "C" void kernel_launch(void* const* d_in, const int* in_sizes, int n_in,
                              void* d_out, int out_size)
{
    const int*   idx     = (const int*)  d_in[0];
    const int*   targets = (const int*)  d_in[1];
    const float* tok_emb = (const float*)d_in[2];
    const float* pos_emb = (const float*)d_in[3];
    const float* ln1_g   = (const float*)d_in[4];
    const float* ln1_b   = (const float*)d_in[5];
    const float* Wq      = (const float*)d_in[6];
    const float* Wk      = (const float*)d_in[7];
    const float* Wv      = (const float*)d_in[8];
    const float* Wp      = (const float*)d_in[9];
    const float* bp      = (const float*)d_in[10];
    const float* ln2_g   = (const float*)d_in[11];
    const float* ln2_b   = (const float*)d_in[12];
    const float* W1      = (const float*)d_in[13];
    const float* b1      = (const float*)d_in[14];
    const float* W2      = (const float*)d_in[15];
    const float* b2      = (const float*)d_in[16];
    const float* lnf_g   = (const float*)d_in[17];
    const float* lnf_b   = (const float*)d_in[18];
    const float* Wlm     = (const float*)d_in[19];
    const float* blm     = (const float*)d_in[20];

    float* out      = (float*)d_out;
    float* attn_out = out + 1;

    float *x, *qkv, *lg, *rl;
    __half *hh, *oh, *ffh, *wth;
    cudaGetSymbolAddress((void**)&x,   g_x);
    cudaGetSymbolAddress((void**)&hh,  g_hh);
    cudaGetSymbolAddress((void**)&qkv, g_qkv);
    cudaGetSymbolAddress((void**)&oh,  g_oh);
    cudaGetSymbolAddress((void**)&ffh, g_ffh);
    cudaGetSymbolAddress((void**)&wth, g_wth);
    cudaGetSymbolAddress((void**)&lg,  g_log);
    cudaGetSymbolAddress((void**)&rl,  g_rl);

    cudaFuncSetAttribute(gemm_mma<0>, cudaFuncAttributeMaxDynamicSharedMemorySize, GEMM_SMEM);
    cudaFuncSetAttribute(gemm_mma<1>, cudaFuncAttributeMaxDynamicSharedMemorySize, GEMM_SMEM);
    cudaFuncSetAttribute(gemm_mma<2>, cudaFuncAttributeMaxDynamicSharedMemorySize, GEMM_SMEM);
    cudaFuncSetAttribute(attn_fused,  cudaFuncAttributeMaxDynamicSharedMemorySize, ATT_SMEM);

    embed_kernel<<<ROWS, 256>>>(idx, tok_emb, pos_emb, x);

    for (int l = 0; l < NL; l++) {
        ln_kernel<<<ROWS, 256>>>(x, ln1_g + (size_t)l * DIM, ln1_b + (size_t)l * DIM, hh);
        pack_qkv_t<<<dim3(3 * DIM, DIM / 256), 256>>>(Wq, Wk, Wv, wth, l);
        gemm_mma<0><<<dim3(3 * DIM / 128, ROWS / 128), 256, GEMM_SMEM>>>(
            hh, wth, nullptr, nullptr, qkv, 3 * DIM, DIM);

        float* attnL = attn_out + (size_t)l * BATCH * NH * SEQ * SEQ;
        attn_fused<<<dim3(SEQ / 8, BATCH * NH), 256, ATT_SMEM>>>(qkv, attnL, oh);

        transpose_k<<<dim3(DIM / 32, DIM / 32), dim3(32, 8)>>>(
            Wp + (size_t)l * DIM * DIM, wth, DIM, DIM);
        gemm_mma<1><<<dim3(DIM / 128, ROWS / 128), 256, GEMM_SMEM>>>(
            oh, wth, bp + (size_t)l * DIM, x, x, DIM, DIM);

        ln_kernel<<<ROWS, 256>>>(x, ln2_g + (size_t)l * DIM, ln2_b + (size_t)l * DIM, hh);

        transpose_k<<<dim3(FFD / 32, DIM / 32), dim3(32, 8)>>>(
            W1 + (size_t)l * DIM * FFD, wth, DIM, FFD);
        gemm_mma<2><<<dim3(FFD / 128, ROWS / 128), 256, GEMM_SMEM>>>(
            hh, wth, b1 + (size_t)l * FFD, nullptr, ffh, FFD, DIM);

        transpose_k<<<dim3(DIM / 32, FFD / 32), dim3(32, 8)>>>(
            W2 + (size_t)l * FFD * DIM, wth, FFD, DIM);
        gemm_mma<1><<<dim3(DIM / 128, ROWS / 128), 256, GEMM_SMEM>>>(
            ffh, wth, b2 + (size_t)l * DIM, x, x, DIM, FFD);
    }

    ln_kernel<<<ROWS, 256>>>(x, lnf_g, lnf_b, hh);
    transpose_k<<<dim3(VOCAB / 32, DIM / 32), dim3(32, 8)>>>(Wlm, wth, DIM, VOCAB);
    gemm_mma<0><<<dim3(VOCAB / 128, ROWS / 128), 256, GEMM_SMEM>>>(
        hh, wth, blm, nullptr, lg, VOCAB, DIM);

    loss_rows_kernel<<<ROWS, 256>>>(lg, targets, rl);
    loss_reduce_kernel<<<1, 256>>>(rl, out);
}

// round 9
// speedup vs baseline: 7.4090x; 1.4450x over previous
#include <cuda_runtime.h>
#include <cuda_fp16.h>
#include <math.h>
#include <stdint.h>

#define BATCH 4
#define SEQ   1024
#define DIM   1024
#define NH    16
#define HS    64
#define NL    4
#define FFD   4096
#define VOCAB 32000
#define ROWS  (BATCH * SEQ)

// ---------------------------------------------------------------------------
// Scratch
// ---------------------------------------------------------------------------
__device__ float  g_x   [(size_t)ROWS * DIM];        // residual (fp32)
__device__ __half g_hh  [(size_t)ROWS * DIM];        // LN output (fp16)
__device__ __half g_qkvh[(size_t)ROWS * 3 * DIM];    // q|k|v per row (fp16)
__device__ __half g_oh  [(size_t)ROWS * DIM];        // attn output (fp16)
__device__ __half g_ffh [(size_t)ROWS * FFD];        // MLP hidden (fp16)
__device__ __half g_wth [(size_t)VOCAB * DIM];       // transposed weights (fp16)
__device__ float  g_log [(size_t)ROWS * VOCAB];      // logits
__device__ float  g_rl  [ROWS];

// ---------------------------------------------------------------------------
// Helpers
// ---------------------------------------------------------------------------
__device__ __forceinline__ uint32_t s2u(const void* p) {
    uint32_t a;
    asm("{ .reg .u64 t; cvta.to.shared.u64 t, %1; cvt.u32.u64 %0, t; }" : "=r"(a) : "l"(p));
    return a;
}
__device__ __forceinline__ void cpa16(uint32_t dst, const void* src) {
    asm volatile("cp.async.cg.shared.global [%0], [%1], 16;" :: "r"(dst), "l"(src));
}
__device__ __forceinline__ void hmma(float* c, uint32_t a0, uint32_t a1, uint32_t a2,
                                     uint32_t a3, uint32_t b0, uint32_t b1) {
    asm volatile(
        "mma.sync.aligned.m16n8k16.row.col.f32.f16.f16.f32 "
        "{%0,%1,%2,%3}, {%4,%5,%6,%7}, {%8,%9}, {%0,%1,%2,%3};"
        : "+f"(c[0]), "+f"(c[1]), "+f"(c[2]), "+f"(c[3])
        : "r"(a0), "r"(a1), "r"(a2), "r"(a3), "r"(b0), "r"(b1));
}
__device__ __forceinline__ void ldsm4(uint32_t* d, uint32_t addr) {
    asm volatile("ldmatrix.sync.aligned.m8n8.x4.shared.b16 {%0,%1,%2,%3}, [%4];"
                 : "=r"(d[0]), "=r"(d[1]), "=r"(d[2]), "=r"(d[3]) : "r"(addr));
}
// e^x for x <= 0, FFMA/ALU-pipe polynomial (relieves MUFU)
__device__ __forceinline__ float exp_poly(float x) {
    float z = x * 1.4426950408889634f;
    float t = z + 12582912.0f;           // round-to-nearest via magic number
    float n = t - 12582912.0f;
    float f = z - n;
    float p = 1.3333558e-3f;
    p = fmaf(p, f, 9.6181291e-3f);
    p = fmaf(p, f, 5.5504109e-2f);
    p = fmaf(p, f, 2.4022651e-1f);
    p = fmaf(p, f, 6.9314718e-1f);
    p = fmaf(p, f, 1.0f);
    float sc = __int_as_float((((int)n) + 127) << 23);
    return (x < -80.f) ? 0.f : p * sc;
}

// ---------------------------------------------------------------------------
// Embedding
// ---------------------------------------------------------------------------
__global__ void embed_kernel(const int* __restrict__ idx,
                             const float* __restrict__ tok,
                             const float* __restrict__ pos,
                             float* __restrict__ x)
{
    int row = blockIdx.x;
    int t   = row & (SEQ - 1);
    int tk  = idx[row];
    const float* te = tok + (size_t)tk * DIM;
    const float* pe = pos + (size_t)t * DIM;
    float* xr = x + (size_t)row * DIM;
    for (int i = threadIdx.x; i < DIM; i += blockDim.x)
        xr[i] = te[i] + pe[i];
}

// ---------------------------------------------------------------------------
// LayerNorm -> fp16
// ---------------------------------------------------------------------------
__global__ void ln_kernel(const float* __restrict__ x,
                          const float* __restrict__ g,
                          const float* __restrict__ b,
                          __half* __restrict__ y)
{
    int row = blockIdx.x;
    int tid = threadIdx.x;
    const float* xr = x + (size_t)row * DIM;
    __half* yr = y + (size_t)row * DIM;

    float s = 0.f, ss = 0.f;
    for (int i = tid; i < DIM; i += 256) {
        float v = xr[i];
        s += v; ss += v * v;
    }
    __shared__ float rs[256], rss[256];
    rs[tid] = s; rss[tid] = ss;
    __syncthreads();
    for (int st = 128; st > 0; st >>= 1) {
        if (tid < st) { rs[tid] += rs[tid + st]; rss[tid] += rss[tid + st]; }
        __syncthreads();
    }
    float mean = rs[0] * (1.0f / DIM);
    float var  = rss[0] * (1.0f / DIM) - mean * mean;
    var = fmaxf(var, 0.f);
    float rstd = rsqrtf(var + 1e-5f);
    for (int i = tid; i < DIM; i += 256)
        yr[i] = __float2half((xr[i] - mean) * rstd * g[i] + b[i]);
}

// ---------------------------------------------------------------------------
// Pack Wq|Wk|Wv -> [3*DIM][DIM] K-major fp16
// ---------------------------------------------------------------------------
__global__ void pack_qkv_t(const float* __restrict__ Wq,
                           const float* __restrict__ Wk,
                           const float* __restrict__ Wv,
                           __half* __restrict__ out, int l)
{
    int c = blockIdx.x;
    int d = blockIdx.y * 256 + threadIdx.x;
    int which = c >> 10;
    int h = (c & 1023) >> 6;
    int s = c & 63;
    const float* W = (which == 0) ? Wq : (which == 1) ? Wk : Wv;
    out[(size_t)c * DIM + d] = __float2half(W[(((size_t)l * NH + h) * DIM + d) * HS + s]);
}

// ---------------------------------------------------------------------------
// Transpose [R][C] fp32 -> [C][R] fp16
// ---------------------------------------------------------------------------
__global__ void transpose_k(const float* __restrict__ in, __half* __restrict__ out,
                            int R, int C)
{
    __shared__ float t[32][33];
    int c0 = blockIdx.x * 32, r0 = blockIdx.y * 32;
    int x = threadIdx.x, y = threadIdx.y;
#pragma unroll
    for (int j = 0; j < 4; j++)
        t[y + 8 * j][x] = in[(size_t)(r0 + y + 8 * j) * C + c0 + x];
    __syncthreads();
#pragma unroll
    for (int j = 0; j < 4; j++)
        out[(size_t)(c0 + y + 8 * j) * R + r0 + x] = __float2half(t[x][y + 8 * j]);
}

// ---------------------------------------------------------------------------
// fp16 HMMA GEMM, ldmatrix fragments, 3-stage cp.async pipeline.
// C[M x N] = A[M x K] @ Bt[N x K]^T
// EPI: 0 = f32 +bias | 1 = f32 +bias+res | 2 = fp16 relu(+bias) | 3 = fp16
// ---------------------------------------------------------------------------
#define PAD 40
#define TILEB (128 * PAD * 2)          // 10240 B per operand tile
#define GEMM_SMEM (6 * TILEB)          // 3 stages x (A,B)

template <int EPI>
__global__ __launch_bounds__(256, 2)
void gemm_mma(const __half* __restrict__ A, const __half* __restrict__ Bt,
              const float* __restrict__ bias, const float* __restrict__ res,
              void* __restrict__ Cv, int N, int K)
{
    extern __shared__ __half smh[];
    uint32_t sA = s2u(smh);
    uint32_t sB = sA + 3 * TILEB;

    const int tid = threadIdx.x;
    const int bn = blockIdx.x * 128;
    const int bm = blockIdx.y * 128;
    const int wid = tid >> 5, l = tid & 31;
    const int wm = (wid & 1) * 64;
    const int wn = (wid >> 1) * 32;
    const int nt = K / 32;

    const int ldr = tid >> 2;
    const int ldc = (tid & 3) * 8;
    const __half* Ag = A  + (size_t)(bm + ldr) * K + ldc;
    const __half* Bg = Bt + (size_t)(bn + ldr) * K + ldc;
    const uint32_t sAo = sA + (ldr * PAD + ldc) * 2;
    const uint32_t sBo = sB + (ldr * PAD + ldc) * 2;

    float acc[4][4][4];
#pragma unroll
    for (int i = 0; i < 4; i++)
#pragma unroll
        for (int j = 0; j < 4; j++)
#pragma unroll
            for (int c = 0; c < 4; c++) acc[i][j][c] = 0.f;

    // ldmatrix per-lane geometry
    const int a_row  = l & 15;
    const int a_koff = (l >> 4) * 8;
    const int b_nrow = (l & 7) + ((l >> 4) << 3);
    const int b_koff = ((l >> 3) & 1) * 8;

#define LOAD_TILE(T)                                                          \
    {                                                                         \
        int buf_ = (T) % 3;                                                   \
        int ko_ = (T) * 32;                                                   \
        _Pragma("unroll")                                                     \
        for (int p = 0; p < 2; p++) {                                         \
            cpa16(sAo + buf_ * TILEB + p * 64 * PAD * 2,                      \
                  Ag + (size_t)(p * 64) * K + ko_);                           \
            cpa16(sBo + buf_ * TILEB + p * 64 * PAD * 2,                      \
                  Bg + (size_t)(p * 64) * K + ko_);                           \
        }                                                                     \
        asm volatile("cp.async.commit_group;" ::: "memory");                  \
    }

    LOAD_TILE(0);
    if (nt > 1) LOAD_TILE(1);

    for (int t = 0; t < nt; t++) {
        if (t + 2 < nt) {
            LOAD_TILE(t + 2);
            asm volatile("cp.async.wait_group 2;" ::: "memory");
        } else if (t + 1 < nt) {
            asm volatile("cp.async.wait_group 1;" ::: "memory");
        } else {
            asm volatile("cp.async.wait_group 0;" ::: "memory");
        }
        __syncthreads();
        uint32_t Ab = sA + (t % 3) * TILEB;
        uint32_t Bb = sB + (t % 3) * TILEB;
#pragma unroll
        for (int kk = 0; kk < 2; kk++) {
            int k0 = kk * 16;
            uint32_t a[4][4], bfr[2][4];
#pragma unroll
            for (int im = 0; im < 4; im++)
                ldsm4(a[im], Ab + ((wm + im * 16 + a_row) * PAD + k0 + a_koff) * 2);
#pragma unroll
            for (int g = 0; g < 2; g++)
                ldsm4(bfr[g], Bb + ((wn + g * 16 + b_nrow) * PAD + k0 + b_koff) * 2);
#pragma unroll
            for (int im = 0; im < 4; im++)
#pragma unroll
                for (int in = 0; in < 4; in++)
                    hmma(acc[im][in], a[im][0], a[im][1], a[im][2], a[im][3],
                         bfr[in >> 1][(in & 1) * 2], bfr[in >> 1][(in & 1) * 2 + 1]);
        }
        __syncthreads();
    }
#undef LOAD_TILE

    float*  Cf = (float*)Cv;
    __half* Ch = (__half*)Cv;
#pragma unroll
    for (int im = 0; im < 4; im++) {
        int r0 = bm + wm + im * 16 + (l >> 2);
#pragma unroll
        for (int in = 0; in < 4; in++) {
            int cc = bn + wn + in * 8 + (l & 3) * 2;
            float b0 = 0.f, b1 = 0.f;
            if (bias) { b0 = bias[cc]; b1 = bias[cc + 1]; }
            float v0 = acc[im][in][0] + b0;
            float v1 = acc[im][in][1] + b1;
            float v2 = acc[im][in][2] + b0;
            float v3 = acc[im][in][3] + b1;
            if (EPI == 1) {
                v0 += res[(size_t)r0 * N + cc];
                v1 += res[(size_t)r0 * N + cc + 1];
                v2 += res[(size_t)(r0 + 8) * N + cc];
                v3 += res[(size_t)(r0 + 8) * N + cc + 1];
            }
            if (EPI == 2 || EPI == 3) {
                if (EPI == 2) {
                    v0 = fmaxf(v0, 0.f); v1 = fmaxf(v1, 0.f);
                    v2 = fmaxf(v2, 0.f); v3 = fmaxf(v3, 0.f);
                }
                *(__half2*)&Ch[(size_t)r0 * N + cc] =
                    __halves2half2(__float2half(v0), __float2half(v1));
                *(__half2*)&Ch[(size_t)(r0 + 8) * N + cc] =
                    __halves2half2(__float2half(v2), __float2half(v3));
            } else {
                *(float2*)&Cf[(size_t)r0 * N + cc] = make_float2(v0, v1);
                *(float2*)&Cf[(size_t)(r0 + 8) * N + cc] = make_float2(v2, v3);
            }
        }
    }
}

// ---------------------------------------------------------------------------
// HMMA attention: 32 q-rows x one (b,h) per CTA.
// scores (HMMA, f32 smem) -> softmax (hybrid exp; probs f32 out + P fp16
// in-place) -> AV (HMMA with smem-transposed V).
// ---------------------------------------------------------------------------
#define SQ 32
#define SPITCH 1032                    // floats per S row
#define KVP 72                         // halves per KV row
#define VTP 136                        // halves per Vt row
#define ATT_SMEM (SQ * SPITCH * 4 + 2 * 128 * KVP * 2 + 64 * VTP * 2 + SQ * KVP * 2)

// load one 128-token x 64-feature fp16 tile (8 x 16B chunks per row)
#define LOAD_KV_TILE(DSTP, GOFF)                                              \
    {                                                                         \
        _Pragma("unroll")                                                     \
        for (int u_ = 0; u_ < 4; u_++) {                                      \
            int c_ = tid + 256 * u_;                                          \
            int tok_ = c_ >> 3, o8_ = (c_ & 7) * 8;                           \
            cpa16(s2u(DSTP) + (tok_ * KVP + o8_) * 2,                         \
                  qkvh + qbase + (GOFF) + (size_t)tok_ * 3072 + o8_);         \
        }                                                                     \
        asm volatile("cp.async.commit_group;" ::: "memory");                  \
    }

__global__ __launch_bounds__(256)
void attn_hmma(const __half* __restrict__ qkvh, float* __restrict__ attn,
               __half* __restrict__ oh)
{
    extern __shared__ float sm[];
    float*  S   = sm;                                  // [32][1032] f32
    __half* KV0 = (__half*)(sm + SQ * SPITCH);         // [128][72]
    __half* KV1 = KV0 + 128 * KVP;
    __half* Vt  = KV1 + 128 * KVP;                     // [64][136]
    __half* Q   = Vt + 64 * VTP;                       // [32][72]

    const int tid = threadIdx.x;
    const int q0 = blockIdx.x * SQ;
    const int bh = blockIdx.y;
    const int b = bh >> 4, hh = bh & 15;
    const int wid = tid >> 5, l = tid & 31;
    const int c2 = (l & 3) * 2;
    const int lq = l >> 2;
    const int ntile = (q0 >> 7) + 1;
    const int region = ntile << 7;
    const size_t qbase = (size_t)(b * SEQ) * 3072 + hh * 64;

    // Q (32 rows x 8 chunks) + K tile 0 in one group
    {
        int r = tid >> 3, c8 = (tid & 7) * 8;
        cpa16(s2u(Q) + (r * KVP + c8) * 2, qkvh + qbase + (size_t)(q0 + r) * 3072 + c8);
    }
    LOAD_KV_TILE(KV0, 1024);

    const int wm = (wid & 1) * 16;
    const int wn = (wid >> 1) * 32;

    // ---- scores ----
    for (int t = 0; t < ntile; t++) {
        if (t + 1 < ntile) {
            __half* KB = ((t + 1) & 1) ? KV1 : KV0;
            size_t goff = 1024 + (size_t)((t + 1) << 7) * 3072;
            LOAD_KV_TILE(KB, goff);
            asm volatile("cp.async.wait_group 1;" ::: "memory");
        } else {
            asm volatile("cp.async.wait_group 0;" ::: "memory");
        }
        __syncthreads();
        const __half* KB = (t & 1) ? KV1 : KV0;
        int kt0 = t << 7;
        float acc[4][4];
#pragma unroll
        for (int in = 0; in < 4; in++)
#pragma unroll
            for (int c = 0; c < 4; c++) acc[in][c] = 0.f;
#pragma unroll
        for (int kk = 0; kk < 4; kk++) {
            int k0 = kk * 16;
            uint32_t a0 = *(const uint32_t*)&Q[(wm + lq) * KVP + k0 + c2];
            uint32_t a1 = *(const uint32_t*)&Q[(wm + lq + 8) * KVP + k0 + c2];
            uint32_t a2 = *(const uint32_t*)&Q[(wm + lq) * KVP + k0 + c2 + 8];
            uint32_t a3 = *(const uint32_t*)&Q[(wm + lq + 8) * KVP + k0 + c2 + 8];
#pragma unroll
            for (int in = 0; in < 4; in++) {
                int n = wn + in * 8 + lq;
                uint32_t b0 = *(const uint32_t*)&KB[n * KVP + k0 + c2];
                uint32_t b1 = *(const uint32_t*)&KB[n * KVP + k0 + c2 + 8];
                hmma(acc[in], a0, a1, a2, a3, b0, b1);
            }
        }
        int qr = wm + lq;
#pragma unroll
        for (int in = 0; in < 4; in++) {
            int kg = kt0 + wn + in * 8 + c2;
            float v0 = (kg     <= q0 + qr)     ? acc[in][0] * 0.125f : -INFINITY;
            float v1 = (kg + 1 <= q0 + qr)     ? acc[in][1] * 0.125f : -INFINITY;
            float v2 = (kg     <= q0 + qr + 8) ? acc[in][2] * 0.125f : -INFINITY;
            float v3 = (kg + 1 <= q0 + qr + 8) ? acc[in][3] * 0.125f : -INFINITY;
            *(float2*)&S[qr * SPITCH + kg]       = make_float2(v0, v1);
            *(float2*)&S[(qr + 8) * SPITCH + kg] = make_float2(v2, v3);
        }
        __syncthreads();
    }

    // prefetch V tile 0 (overlaps softmax)
    LOAD_KV_TILE(KV0, 2048);

    // ---- softmax: warp wid handles rows 4*wid .. 4*wid+3 ----
    for (int rr = 0; rr < 4; rr++) {
        int q = wid * 4 + rr;
        int qt = q0 + q;
        float* Sr = S + q * SPITCH;
        float m = -INFINITY;
        for (int j = l; j <= qt; j += 32) m = fmaxf(m, Sr[j]);
#pragma unroll
        for (int st = 16; st > 0; st >>= 1)
            m = fmaxf(m, __shfl_xor_sync(0xFFFFFFFF, m, st));
        float ssum = 0.f;
        int it = 0;
        for (int j = l; j <= qt; j += 32, it++) {
            float d = Sr[j] - m;
            float e = (it & 1) ? exp_poly(d) : __expf(d);
            Sr[j] = e;
            ssum += e;
        }
#pragma unroll
        for (int st = 16; st > 0; st >>= 1)
            ssum += __shfl_xor_sync(0xFFFFFFFF, ssum, st);
        float inv = 1.0f / ssum;
        __half* Pr = (__half*)Sr;
        float* dst = attn + ((size_t)bh * SEQ + qt) * SEQ;
        for (int j = l; j < region; j += 32) {
            float p = (j <= qt) ? Sr[j] * inv : 0.f;
            dst[j] = p;
            Pr[j] = __float2half(p);
        }
        for (int j = region + l; j < SEQ; j += 32) dst[j] = 0.f;
    }
    __syncthreads();

    // ---- AV ----
    const int wn2 = (wid >> 1) * 16;
    const __half* Ph = (const __half*)S;               // pitch 2064 halves
    float oacc[2][4];
#pragma unroll
    for (int in = 0; in < 2; in++)
#pragma unroll
        for (int c = 0; c < 4; c++) oacc[in][c] = 0.f;

    for (int t = 0; t < ntile; t++) {
        if (t + 1 < ntile) {
            __half* KB = ((t + 1) & 1) ? KV1 : KV0;
            size_t goff = 2048 + (size_t)((t + 1) << 7) * 3072;
            LOAD_KV_TILE(KB, goff);
            asm volatile("cp.async.wait_group 1;" ::: "memory");
        } else {
            asm volatile("cp.async.wait_group 0;" ::: "memory");
        }
        __syncthreads();
        // transpose KV[t&1] -> Vt
        const __half* KB = (t & 1) ? KV1 : KV0;
#pragma unroll
        for (int u = 0; u < 16; u++) {
            int i = tid + 256 * u;
            int s2 = i & 31, tok = i >> 5;
            __half2 v = *(const __half2*)&KB[tok * KVP + s2 * 2];
            Vt[(s2 * 2) * VTP + tok]     = __low2half(v);
            Vt[(s2 * 2 + 1) * VTP + tok] = __high2half(v);
        }
        __syncthreads();
        int kt0 = t << 7;
#pragma unroll
        for (int kk = 0; kk < 8; kk++) {
            int k0 = kk * 16;
            uint32_t a0 = *(const uint32_t*)&Ph[(wm + lq) * (SPITCH * 2) + kt0 + k0 + c2];
            uint32_t a1 = *(const uint32_t*)&Ph[(wm + lq + 8) * (SPITCH * 2) + kt0 + k0 + c2];
            uint32_t a2 = *(const uint32_t*)&Ph[(wm + lq) * (SPITCH * 2) + kt0 + k0 + c2 + 8];
            uint32_t a3 = *(const uint32_t*)&Ph[(wm + lq + 8) * (SPITCH * 2) + kt0 + k0 + c2 + 8];
#pragma unroll
            for (int in = 0; in < 2; in++) {
                int s = wn2 + in * 8 + lq;
                uint32_t b0 = *(const uint32_t*)&Vt[s * VTP + k0 + c2];
                uint32_t b1 = *(const uint32_t*)&Vt[s * VTP + k0 + c2 + 8];
                hmma(oacc[in], a0, a1, a2, a3, b0, b1);
            }
        }
        __syncthreads();
    }
    // write O (fp16)
#pragma unroll
    for (int in = 0; in < 2; in++) {
        int q = q0 + wm + lq;
        int s = wn2 + in * 8 + c2;
        *(__half2*)&oh[(size_t)(b * SEQ + q) * DIM + hh * 64 + s] =
            __halves2half2(__float2half(oacc[in][0]), __float2half(oacc[in][1]));
        *(__half2*)&oh[(size_t)(b * SEQ + q + 8) * DIM + hh * 64 + s] =
            __halves2half2(__float2half(oacc[in][2]), __float2half(oacc[in][3]));
    }
}
#undef LOAD_KV_TILE

// ---------------------------------------------------------------------------
// Loss: online logsumexp, hybrid MUFU/poly exp
// ---------------------------------------------------------------------------
__global__ __launch_bounds__(256)
void loss_rows_kernel(const float* __restrict__ logits,
                      const int* __restrict__ targets,
                      float* __restrict__ rowloss)
{
    int row = blockIdx.x;
    int tid = threadIdx.x;
    const float* lr = logits + (size_t)row * VOCAB;

    float m = -INFINITY, s = 0.f;
    int it = 0;
    for (int v = tid; v < VOCAB; v += 256, it++) {
        float z = lr[v];
        if (z > m) {
            float d = m - z;
            float e = (it & 1) ? exp_poly(d) : __expf(d);
            s = s * e + 1.f;
            m = z;
        } else {
            float d = z - m;
            s += (it & 1) ? exp_poly(d) : __expf(d);
        }
    }
    __shared__ float ms[256], ss[256];
    ms[tid] = m; ss[tid] = s;
    __syncthreads();
    for (int st = 128; st > 0; st >>= 1) {
        if (tid < st) {
            float m2 = ms[tid + st], s2 = ss[tid + st];
            float M = fmaxf(ms[tid], m2);
            ss[tid] = ss[tid] * __expf(ms[tid] - M) + s2 * __expf(m2 - M);
            ms[tid] = M;
        }
        __syncthreads();
    }
    if (tid == 0) {
        float zt = lr[targets[row]];
        rowloss[row] = ms[0] + logf(ss[0]) - zt;
    }
}

__global__ void loss_reduce_kernel(const float* __restrict__ rowloss, float* __restrict__ out)
{
    __shared__ float red[256];
    int tid = threadIdx.x;
    float s = 0.f;
    for (int i = tid; i < ROWS; i += 256) s += rowloss[i];
    red[tid] = s;
    __syncthreads();
    for (int st = 128; st > 0; st >>= 1) {
        if (tid < st) red[tid] += red[tid + st];
        __syncthreads();
    }
    if (tid == 0) out[0] = red[0] * (1.0f / ROWS);
}

// ---------------------------------------------------------------------------
// Host
// ---------------------------------------------------------------------------
extern "C" void kernel_launch(void* const* d_in, const int* in_sizes, int n_in,
                              void* d_out, int out_size)
{
    const int*   idx     = (const int*)  d_in[0];
    const int*   targets = (const int*)  d_in[1];
    const float* tok_emb = (const float*)d_in[2];
    const float* pos_emb = (const float*)d_in[3];
    const float* ln1_g   = (const float*)d_in[4];
    const float* ln1_b   = (const float*)d_in[5];
    const float* Wq      = (const float*)d_in[6];
    const float* Wk      = (const float*)d_in[7];
    const float* Wv      = (const float*)d_in[8];
    const float* Wp      = (const float*)d_in[9];
    const float* bp      = (const float*)d_in[10];
    const float* ln2_g   = (const float*)d_in[11];
    const float* ln2_b   = (const float*)d_in[12];
    const float* W1      = (const float*)d_in[13];
    const float* b1      = (const float*)d_in[14];
    const float* W2      = (const float*)d_in[15];
    const float* b2      = (const float*)d_in[16];
    const float* lnf_g   = (const float*)d_in[17];
    const float* lnf_b   = (const float*)d_in[18];
    const float* Wlm     = (const float*)d_in[19];
    const float* blm     = (const float*)d_in[20];

    float* out      = (float*)d_out;
    float* attn_out = out + 1;

    float *x, *lg, *rl;
    __half *hbuf, *qkvh, *ohb, *ffh, *wth;
    cudaGetSymbolAddress((void**)&x,    g_x);
    cudaGetSymbolAddress((void**)&hbuf, g_hh);
    cudaGetSymbolAddress((void**)&qkvh, g_qkvh);
    cudaGetSymbolAddress((void**)&ohb,  g_oh);
    cudaGetSymbolAddress((void**)&ffh,  g_ffh);
    cudaGetSymbolAddress((void**)&wth,  g_wth);
    cudaGetSymbolAddress((void**)&lg,   g_log);
    cudaGetSymbolAddress((void**)&rl,   g_rl);

    cudaFuncSetAttribute(gemm_mma<0>, cudaFuncAttributeMaxDynamicSharedMemorySize, GEMM_SMEM);
    cudaFuncSetAttribute(gemm_mma<1>, cudaFuncAttributeMaxDynamicSharedMemorySize, GEMM_SMEM);
    cudaFuncSetAttribute(gemm_mma<2>, cudaFuncAttributeMaxDynamicSharedMemorySize, GEMM_SMEM);
    cudaFuncSetAttribute(gemm_mma<3>, cudaFuncAttributeMaxDynamicSharedMemorySize, GEMM_SMEM);
    cudaFuncSetAttribute(attn_hmma,   cudaFuncAttributeMaxDynamicSharedMemorySize, ATT_SMEM);

    embed_kernel<<<ROWS, 256>>>(idx, tok_emb, pos_emb, x);

    for (int l = 0; l < NL; l++) {
        ln_kernel<<<ROWS, 256>>>(x, ln1_g + (size_t)l * DIM, ln1_b + (size_t)l * DIM, hbuf);
        pack_qkv_t<<<dim3(3 * DIM, DIM / 256), 256>>>(Wq, Wk, Wv, wth, l);
        gemm_mma<3><<<dim3(3 * DIM / 128, ROWS / 128), 256, GEMM_SMEM>>>(
            hbuf, wth, nullptr, nullptr, qkvh, 3 * DIM, DIM);

        float* attnL = attn_out + (size_t)l * BATCH * NH * SEQ * SEQ;
        attn_hmma<<<dim3(SEQ / SQ, BATCH * NH), 256, ATT_SMEM>>>(qkvh, attnL, ohb);

        transpose_k<<<dim3(DIM / 32, DIM / 32), dim3(32, 8)>>>(
            Wp + (size_t)l * DIM * DIM, wth, DIM, DIM);
        gemm_mma<1><<<dim3(DIM / 128, ROWS / 128), 256, GEMM_SMEM>>>(
            ohb, wth, bp + (size_t)l * DIM, x, x, DIM, DIM);

        ln_kernel<<<ROWS, 256>>>(x, ln2_g + (size_t)l * DIM, ln2_b + (size_t)l * DIM, hbuf);

        transpose_k<<<dim3(FFD / 32, DIM / 32), dim3(32, 8)>>>(
            W1 + (size_t)l * DIM * FFD, wth, DIM, FFD);
        gemm_mma<2><<<dim3(FFD / 128, ROWS / 128), 256, GEMM_SMEM>>>(
            hbuf, wth, b1 + (size_t)l * FFD, nullptr, ffh, FFD, DIM);

        transpose_k<<<dim3(DIM / 32, FFD / 32), dim3(32, 8)>>>(
            W2 + (size_t)l * FFD * DIM, wth, FFD, DIM);
        gemm_mma<1><<<dim3(DIM / 128, ROWS / 128), 256, GEMM_SMEM>>>(
            ffh, wth, b2 + (size_t)l * DIM, x, x, DIM, FFD);
    }

    ln_kernel<<<ROWS, 256>>>(x, lnf_g, lnf_b, hbuf);
    transpose_k<<<dim3(VOCAB / 32, DIM / 32), dim3(32, 8)>>>(Wlm, wth, DIM, VOCAB);
    gemm_mma<0><<<dim3(VOCAB / 128, ROWS / 128), 256, GEMM_SMEM>>>(
        hbuf, wth, blm, nullptr, lg, VOCAB, DIM);

    loss_rows_kernel<<<ROWS, 256>>>(lg, targets, rl);
    loss_reduce_kernel<<<1, 256>>>(rl, out);
}

// round 10
// speedup vs baseline: 7.9690x; 1.0756x over previous
#include <cuda_runtime.h>
#include <cuda_fp16.h>
#include <math.h>
#include <stdint.h>

#define BATCH 4
#define SEQ   1024
#define DIM   1024
#define NH    16
#define HS    64
#define NL    4
#define FFD   4096
#define VOCAB 32000
#define ROWS  (BATCH * SEQ)
#define NSLAB (VOCAB / 128)            // 250

// ---------------------------------------------------------------------------
// Scratch
// ---------------------------------------------------------------------------
__device__ float  g_x   [(size_t)ROWS * DIM];        // residual (fp32)
__device__ __half g_hh  [(size_t)ROWS * DIM];        // LN output (fp16)
__device__ __half g_qkvh[(size_t)ROWS * 3 * DIM];    // q|k|v per row (fp16)
__device__ __half g_oh  [(size_t)ROWS * DIM];        // attn output (fp16)
__device__ __half g_ffh [(size_t)ROWS * FFD];        // MLP hidden (fp16)
__device__ __half g_wth [(size_t)VOCAB * DIM];       // transposed weights (fp16)
__device__ float2 g_part[(size_t)ROWS * NSLAB];      // per-slab (max, sumexp)
__device__ float  g_zt  [ROWS];                      // target logits
__device__ float  g_rl  [ROWS];

// ---------------------------------------------------------------------------
// Helpers
// ---------------------------------------------------------------------------
__device__ __forceinline__ uint32_t s2u(const void* p) {
    uint32_t a;
    asm("{ .reg .u64 t; cvta.to.shared.u64 t, %1; cvt.u32.u64 %0, t; }" : "=r"(a) : "l"(p));
    return a;
}
__device__ __forceinline__ void cpa16(uint32_t dst, const void* src) {
    asm volatile("cp.async.cg.shared.global [%0], [%1], 16;" :: "r"(dst), "l"(src));
}
__device__ __forceinline__ void hmma(float* c, uint32_t a0, uint32_t a1, uint32_t a2,
                                     uint32_t a3, uint32_t b0, uint32_t b1) {
    asm volatile(
        "mma.sync.aligned.m16n8k16.row.col.f32.f16.f16.f32 "
        "{%0,%1,%2,%3}, {%4,%5,%6,%7}, {%8,%9}, {%0,%1,%2,%3};"
        : "+f"(c[0]), "+f"(c[1]), "+f"(c[2]), "+f"(c[3])
        : "r"(a0), "r"(a1), "r"(a2), "r"(a3), "r"(b0), "r"(b1));
}
__device__ __forceinline__ void ldsm4(uint32_t* d, uint32_t addr) {
    asm volatile("ldmatrix.sync.aligned.m8n8.x4.shared.b16 {%0,%1,%2,%3}, [%4];"
                 : "=r"(d[0]), "=r"(d[1]), "=r"(d[2]), "=r"(d[3]) : "r"(addr));
}
// e^x for x <= 0, FFMA/ALU-pipe polynomial (relieves MUFU)
__device__ __forceinline__ float exp_poly(float x) {
    float z = x * 1.4426950408889634f;
    float t = z + 12582912.0f;
    float n = t - 12582912.0f;
    float f = z - n;
    float p = 1.3333558e-3f;
    p = fmaf(p, f, 9.6181291e-3f);
    p = fmaf(p, f, 5.5504109e-2f);
    p = fmaf(p, f, 2.4022651e-1f);
    p = fmaf(p, f, 6.9314718e-1f);
    p = fmaf(p, f, 1.0f);
    float sc = __int_as_float((((int)n) + 127) << 23);
    return (x < -80.f) ? 0.f : p * sc;
}

// ---------------------------------------------------------------------------
// Embedding
// ---------------------------------------------------------------------------
__global__ void embed_kernel(const int* __restrict__ idx,
                             const float* __restrict__ tok,
                             const float* __restrict__ pos,
                             float* __restrict__ x)
{
    int row = blockIdx.x;
    int t   = row & (SEQ - 1);
    int tk  = idx[row];
    const float* te = tok + (size_t)tk * DIM;
    const float* pe = pos + (size_t)t * DIM;
    float* xr = x + (size_t)row * DIM;
    for (int i = threadIdx.x; i < DIM; i += blockDim.x)
        xr[i] = te[i] + pe[i];
}

// ---------------------------------------------------------------------------
// LayerNorm -> fp16
// ---------------------------------------------------------------------------
__global__ void ln_kernel(const float* __restrict__ x,
                          const float* __restrict__ g,
                          const float* __restrict__ b,
                          __half* __restrict__ y)
{
    int row = blockIdx.x;
    int tid = threadIdx.x;
    const float* xr = x + (size_t)row * DIM;
    __half* yr = y + (size_t)row * DIM;

    float s = 0.f, ss = 0.f;
    for (int i = tid; i < DIM; i += 256) {
        float v = xr[i];
        s += v; ss += v * v;
    }
    __shared__ float rs[256], rss[256];
    rs[tid] = s; rss[tid] = ss;
    __syncthreads();
    for (int st = 128; st > 0; st >>= 1) {
        if (tid < st) { rs[tid] += rs[tid + st]; rss[tid] += rss[tid + st]; }
        __syncthreads();
    }
    float mean = rs[0] * (1.0f / DIM);
    float var  = rss[0] * (1.0f / DIM) - mean * mean;
    var = fmaxf(var, 0.f);
    float rstd = rsqrtf(var + 1e-5f);
    for (int i = tid; i < DIM; i += 256)
        yr[i] = __float2half((xr[i] - mean) * rstd * g[i] + b[i]);
}

// ---------------------------------------------------------------------------
// Pack Wq|Wk|Wv -> [3*DIM][DIM] K-major fp16
// ---------------------------------------------------------------------------
__global__ void pack_qkv_t(const float* __restrict__ Wq,
                           const float* __restrict__ Wk,
                           const float* __restrict__ Wv,
                           __half* __restrict__ out, int l)
{
    int c = blockIdx.x;
    int d = blockIdx.y * 256 + threadIdx.x;
    int which = c >> 10;
    int h = (c & 1023) >> 6;
    int s = c & 63;
    const float* W = (which == 0) ? Wq : (which == 1) ? Wk : Wv;
    out[(size_t)c * DIM + d] = __float2half(W[(((size_t)l * NH + h) * DIM + d) * HS + s]);
}

// ---------------------------------------------------------------------------
// Transpose [R][C] fp32 -> [C][R] fp16
// ---------------------------------------------------------------------------
__global__ void transpose_k(const float* __restrict__ in, __half* __restrict__ out,
                            int R, int C)
{
    __shared__ float t[32][33];
    int c0 = blockIdx.x * 32, r0 = blockIdx.y * 32;
    int x = threadIdx.x, y = threadIdx.y;
#pragma unroll
    for (int j = 0; j < 4; j++)
        t[y + 8 * j][x] = in[(size_t)(r0 + y + 8 * j) * C + c0 + x];
    __syncthreads();
#pragma unroll
    for (int j = 0; j < 4; j++)
        out[(size_t)(c0 + y + 8 * j) * R + r0 + x] = __float2half(t[x][y + 8 * j]);
}

// ---------------------------------------------------------------------------
// fp16 HMMA GEMM, ldmatrix fragments, 3-stage pipeline, 1 sync per tile.
// C[M x N] = A[M x K] @ Bt[N x K]^T
// EPI: 0 = f32 +bias | 1 = f32 +bias+res | 2 = fp16 relu(+bias) | 3 = fp16
// ---------------------------------------------------------------------------
#define PAD 40
#define TILEB (128 * PAD * 2)          // 10240 B per operand tile
#define GEMM_SMEM (6 * TILEB)          // 3 stages x (A,B)

#define GEMM_PRE()                                                            \
    extern __shared__ __half smh[];                                           \
    uint32_t sA = s2u(smh);                                                   \
    uint32_t sB = sA + 3 * TILEB;                                             \
    const int tid = threadIdx.x;                                              \
    const int bn = blockIdx.x * 128;                                          \
    const int bm = blockIdx.y * 128;                                          \
    const int wid = tid >> 5, l = tid & 31;                                   \
    const int wm = (wid & 1) * 64;                                            \
    const int wn = (wid >> 1) * 32;                                           \
    const int nt = K / 32;                                                    \
    const int c2 = (l & 3) * 2;                                               \
    const int lq = l >> 2;                                                    \
    const int ldr = tid >> 2;                                                 \
    const int ldc = (tid & 3) * 8;                                            \
    const __half* Ag = A  + (size_t)(bm + ldr) * K + ldc;                     \
    const __half* Bg = Bt + (size_t)(bn + ldr) * K + ldc;                     \
    const uint32_t sAo = sA + (ldr * PAD + ldc) * 2;                          \
    const uint32_t sBo = sB + (ldr * PAD + ldc) * 2;                          \
    float acc[4][4][4];                                                       \
    _Pragma("unroll")                                                         \
    for (int i = 0; i < 4; i++)                                               \
        _Pragma("unroll")                                                     \
        for (int j = 0; j < 4; j++)                                           \
            _Pragma("unroll")                                                 \
            for (int c = 0; c < 4; c++) acc[i][j][c] = 0.f;                   \
    const int a_row  = l & 15;                                                \
    const int a_koff = (l >> 4) * 8;                                          \
    const int b_nrow = (l & 7) + ((l >> 4) << 3);                             \
    const int b_koff = ((l >> 3) & 1) * 8;

#define LOAD_TILE(T)                                                          \
    {                                                                         \
        int buf_ = (T) % 3;                                                   \
        int ko_ = (T) * 32;                                                   \
        _Pragma("unroll")                                                     \
        for (int p = 0; p < 2; p++) {                                         \
            cpa16(sAo + buf_ * TILEB + p * 64 * PAD * 2,                      \
                  Ag + (size_t)(p * 64) * K + ko_);                           \
            cpa16(sBo + buf_ * TILEB + p * 64 * PAD * 2,                      \
                  Bg + (size_t)(p * 64) * K + ko_);                           \
        }                                                                     \
        asm volatile("cp.async.commit_group;" ::: "memory");                  \
    }

#define GEMM_MAINLOOP()                                                       \
    LOAD_TILE(0);                                                             \
    if (nt > 1) LOAD_TILE(1);                                                 \
    for (int t = 0; t < nt; t++) {                                            \
        if (t + 1 < nt) { asm volatile("cp.async.wait_group 1;" ::: "memory"); } \
        else            { asm volatile("cp.async.wait_group 0;" ::: "memory"); } \
        __syncthreads();                                                      \
        if (t + 2 < nt) LOAD_TILE(t + 2);                                     \
        uint32_t Ab = sA + (t % 3) * TILEB;                                   \
        uint32_t Bb = sB + (t % 3) * TILEB;                                   \
        _Pragma("unroll")                                                     \
        for (int kk = 0; kk < 2; kk++) {                                      \
            int k0 = kk * 16;                                                 \
            uint32_t a[4][4], bfr[2][4];                                      \
            _Pragma("unroll")                                                 \
            for (int im = 0; im < 4; im++)                                    \
                ldsm4(a[im], Ab + ((wm + im * 16 + a_row) * PAD + k0 + a_koff) * 2); \
            _Pragma("unroll")                                                 \
            for (int g = 0; g < 2; g++)                                       \
                ldsm4(bfr[g], Bb + ((wn + g * 16 + b_nrow) * PAD + k0 + b_koff) * 2); \
            _Pragma("unroll")                                                 \
            for (int im = 0; im < 4; im++)                                    \
                _Pragma("unroll")                                             \
                for (int in = 0; in < 4; in++)                                \
                    hmma(acc[im][in], a[im][0], a[im][1], a[im][2], a[im][3], \
                         bfr[in >> 1][(in & 1) * 2], bfr[in >> 1][(in & 1) * 2 + 1]); \
        }                                                                     \
    }

template <int EPI>
__global__ __launch_bounds__(256, 2)
void gemm_mma(const __half* __restrict__ A, const __half* __restrict__ Bt,
              const float* __restrict__ bias, const float* __restrict__ res,
              void* __restrict__ Cv, int N, int K)
{
    GEMM_PRE();
    GEMM_MAINLOOP();

    float*  Cf = (float*)Cv;
    __half* Ch = (__half*)Cv;
#pragma unroll
    for (int im = 0; im < 4; im++) {
        int r0 = bm + wm + im * 16 + lq;
#pragma unroll
        for (int in = 0; in < 4; in++) {
            int cc = bn + wn + in * 8 + c2;
            float b0 = 0.f, b1 = 0.f;
            if (bias) { b0 = bias[cc]; b1 = bias[cc + 1]; }
            float v0 = acc[im][in][0] + b0;
            float v1 = acc[im][in][1] + b1;
            float v2 = acc[im][in][2] + b0;
            float v3 = acc[im][in][3] + b1;
            if (EPI == 1) {
                v0 += res[(size_t)r0 * N + cc];
                v1 += res[(size_t)r0 * N + cc + 1];
                v2 += res[(size_t)(r0 + 8) * N + cc];
                v3 += res[(size_t)(r0 + 8) * N + cc + 1];
            }
            if (EPI == 2 || EPI == 3) {
                if (EPI == 2) {
                    v0 = fmaxf(v0, 0.f); v1 = fmaxf(v1, 0.f);
                    v2 = fmaxf(v2, 0.f); v3 = fmaxf(v3, 0.f);
                }
                *(__half2*)&Ch[(size_t)r0 * N + cc] =
                    __halves2half2(__float2half(v0), __float2half(v1));
                *(__half2*)&Ch[(size_t)(r0 + 8) * N + cc] =
                    __halves2half2(__float2half(v2), __float2half(v3));
            } else {
                *(float2*)&Cf[(size_t)r0 * N + cc] = make_float2(v0, v1);
                *(float2*)&Cf[(size_t)(r0 + 8) * N + cc] = make_float2(v2, v3);
            }
        }
    }
}

// ---------------------------------------------------------------------------
// LM-head GEMM with fused logsumexp partials + target-logit capture.
// Writes per-(row, slab) (max, sumexp) float2; never materializes logits.
// ---------------------------------------------------------------------------
__global__ __launch_bounds__(256, 2)
void gemm_lm(const __half* __restrict__ A, const __half* __restrict__ Bt,
             const float* __restrict__ bias, const int* __restrict__ targets,
             float2* __restrict__ part, float* __restrict__ zt, int K)
{
    GEMM_PRE();
    GEMM_MAINLOOP();

    // bias add + target capture
#pragma unroll
    for (int im = 0; im < 4; im++) {
        int r0g = bm + wm + im * 16 + lq;
        int r1g = r0g + 8;
        int t0 = targets[r0g], t1 = targets[r1g];
#pragma unroll
        for (int in = 0; in < 4; in++) {
            int cc = bn + wn + in * 8 + c2;
            float b0 = bias[cc], b1 = bias[cc + 1];
            acc[im][in][0] += b0; acc[im][in][1] += b1;
            acc[im][in][2] += b0; acc[im][in][3] += b1;
            if (cc     == t0) zt[r0g] = acc[im][in][0];
            if (cc + 1 == t0) zt[r0g] = acc[im][in][1];
            if (cc     == t1) zt[r1g] = acc[im][in][2];
            if (cc + 1 == t1) zt[r1g] = acc[im][in][3];
        }
    }

    float* redM = (float*)smh;             // [128][4]
    float* redS = redM + 512;              // [128][4]
    __syncthreads();                       // all ldsm of last tile done

    // per-row max over this CTA's 128 cols
#pragma unroll
    for (int im = 0; im < 4; im++)
#pragma unroll
        for (int h = 0; h < 2; h++) {
            float mx = -INFINITY;
#pragma unroll
            for (int in = 0; in < 4; in++)
                mx = fmaxf(mx, fmaxf(acc[im][in][h * 2], acc[im][in][h * 2 + 1]));
            mx = fmaxf(mx, __shfl_xor_sync(0xFFFFFFFF, mx, 1));
            mx = fmaxf(mx, __shfl_xor_sync(0xFFFFFFFF, mx, 2));
            int row = wm + im * 16 + lq + h * 8;
            if ((l & 3) == 0) redM[row * 4 + (wid >> 1)] = mx;
        }
    __syncthreads();

    // per-row sumexp
#pragma unroll
    for (int im = 0; im < 4; im++)
#pragma unroll
        for (int h = 0; h < 2; h++) {
            int row = wm + im * 16 + lq + h * 8;
            float rm = fmaxf(fmaxf(redM[row * 4 + 0], redM[row * 4 + 1]),
                             fmaxf(redM[row * 4 + 2], redM[row * 4 + 3]));
            float se = 0.f;
#pragma unroll
            for (int in = 0; in < 4; in++) {
                float d0 = acc[im][in][h * 2]     - rm;
                float d1 = acc[im][in][h * 2 + 1] - rm;
                if (in & 1) { se += exp_poly(d0); se += exp_poly(d1); }
                else        { se += __expf(d0);   se += __expf(d1);   }
            }
            se += __shfl_xor_sync(0xFFFFFFFF, se, 1);
            se += __shfl_xor_sync(0xFFFFFFFF, se, 2);
            if ((l & 3) == 0) redS[row * 4 + (wid >> 1)] = se;
        }
    __syncthreads();

    if (tid < 128) {
        float m = fmaxf(fmaxf(redM[tid * 4 + 0], redM[tid * 4 + 1]),
                        fmaxf(redM[tid * 4 + 2], redM[tid * 4 + 3]));
        float s = redS[tid * 4 + 0] + redS[tid * 4 + 1]
                + redS[tid * 4 + 2] + redS[tid * 4 + 3];
        part[(size_t)(bm + tid) * NSLAB + blockIdx.x] = make_float2(m, s);
    }
}

// ---------------------------------------------------------------------------
// HMMA attention: 32 q-rows x one (b,h) per CTA.
// ---------------------------------------------------------------------------
#define SQ 32
#define SPITCH 1032                    // floats per S row
#define KVP 72                         // halves per KV row
#define VTP 136                        // halves per Vt row
#define ATT_SMEM (SQ * SPITCH * 4 + 2 * 128 * KVP * 2 + 64 * VTP * 2 + SQ * KVP * 2)

#define LOAD_KV_TILE(DSTP, GOFF)                                              \
    {                                                                         \
        _Pragma("unroll")                                                     \
        for (int u_ = 0; u_ < 4; u_++) {                                      \
            int c_ = tid + 256 * u_;                                          \
            int tok_ = c_ >> 3, o8_ = (c_ & 7) * 8;                           \
            cpa16(s2u(DSTP) + (tok_ * KVP + o8_) * 2,                         \
                  qkvh + qbase + (GOFF) + (size_t)tok_ * 3072 + o8_);         \
        }                                                                     \
        asm volatile("cp.async.commit_group;" ::: "memory");                  \
    }

__global__ __launch_bounds__(256)
void attn_hmma(const __half* __restrict__ qkvh, float* __restrict__ attn,
               __half* __restrict__ oh)
{
    extern __shared__ float sm[];
    float*  S   = sm;                                  // [32][1032] f32
    __half* KV0 = (__half*)(sm + SQ * SPITCH);         // [128][72]
    __half* KV1 = KV0 + 128 * KVP;
    __half* Vt  = KV1 + 128 * KVP;                     // [64][136]
    __half* Q   = Vt + 64 * VTP;                       // [32][72]

    const int tid = threadIdx.x;
    const int q0 = blockIdx.x * SQ;
    const int bh = blockIdx.y;
    const int b = bh >> 4, hh = bh & 15;
    const int wid = tid >> 5, l = tid & 31;
    const int c2 = (l & 3) * 2;
    const int lq = l >> 2;
    const int ntile = (q0 >> 7) + 1;
    const int region = ntile << 7;
    const size_t qbase = (size_t)(b * SEQ) * 3072 + hh * 64;

    {
        int r = tid >> 3, c8 = (tid & 7) * 8;
        cpa16(s2u(Q) + (r * KVP + c8) * 2, qkvh + qbase + (size_t)(q0 + r) * 3072 + c8);
    }
    LOAD_KV_TILE(KV0, 1024);

    const int wm = (wid & 1) * 16;
    const int wn = (wid >> 1) * 32;

    // ---- scores ----
    for (int t = 0; t < ntile; t++) {
        if (t + 1 < ntile) {
            __half* KB = ((t + 1) & 1) ? KV1 : KV0;
            size_t goff = 1024 + (size_t)((t + 1) << 7) * 3072;
            LOAD_KV_TILE(KB, goff);
            asm volatile("cp.async.wait_group 1;" ::: "memory");
        } else {
            asm volatile("cp.async.wait_group 0;" ::: "memory");
        }
        __syncthreads();
        const __half* KB = (t & 1) ? KV1 : KV0;
        int kt0 = t << 7;
        float acc[4][4];
#pragma unroll
        for (int in = 0; in < 4; in++)
#pragma unroll
            for (int c = 0; c < 4; c++) acc[in][c] = 0.f;
#pragma unroll
        for (int kk = 0; kk < 4; kk++) {
            int k0 = kk * 16;
            uint32_t a0 = *(const uint32_t*)&Q[(wm + lq) * KVP + k0 + c2];
            uint32_t a1 = *(const uint32_t*)&Q[(wm + lq + 8) * KVP + k0 + c2];
            uint32_t a2 = *(const uint32_t*)&Q[(wm + lq) * KVP + k0 + c2 + 8];
            uint32_t a3 = *(const uint32_t*)&Q[(wm + lq + 8) * KVP + k0 + c2 + 8];
#pragma unroll
            for (int in = 0; in < 4; in++) {
                int n = wn + in * 8 + lq;
                uint32_t b0 = *(const uint32_t*)&KB[n * KVP + k0 + c2];
                uint32_t b1 = *(const uint32_t*)&KB[n * KVP + k0 + c2 + 8];
                hmma(acc[in], a0, a1, a2, a3, b0, b1);
            }
        }
        int qr = wm + lq;
#pragma unroll
        for (int in = 0; in < 4; in++) {
            int kg = kt0 + wn + in * 8 + c2;
            float v0 = (kg     <= q0 + qr)     ? acc[in][0] * 0.125f : -INFINITY;
            float v1 = (kg + 1 <= q0 + qr)     ? acc[in][1] * 0.125f : -INFINITY;
            float v2 = (kg     <= q0 + qr + 8) ? acc[in][2] * 0.125f : -INFINITY;
            float v3 = (kg + 1 <= q0 + qr + 8) ? acc[in][3] * 0.125f : -INFINITY;
            *(float2*)&S[qr * SPITCH + kg]       = make_float2(v0, v1);
            *(float2*)&S[(qr + 8) * SPITCH + kg] = make_float2(v2, v3);
        }
        __syncthreads();
    }

    // prefetch V tile 0 (overlaps softmax)
    LOAD_KV_TILE(KV0, 2048);

    // ---- softmax ----
    for (int rr = 0; rr < 4; rr++) {
        int q = wid * 4 + rr;
        int qt = q0 + q;
        float* Sr = S + q * SPITCH;
        float m = -INFINITY;
        for (int j = l; j <= qt; j += 32) m = fmaxf(m, Sr[j]);
#pragma unroll
        for (int st = 16; st > 0; st >>= 1)
            m = fmaxf(m, __shfl_xor_sync(0xFFFFFFFF, m, st));
        float ssum = 0.f;
        int it = 0;
        for (int j = l; j <= qt; j += 32, it++) {
            float d = Sr[j] - m;
            float e = (it & 1) ? exp_poly(d) : __expf(d);
            Sr[j] = e;
            ssum += e;
        }
#pragma unroll
        for (int st = 16; st > 0; st >>= 1)
            ssum += __shfl_xor_sync(0xFFFFFFFF, ssum, st);
        float inv = 1.0f / ssum;
        __half* Pr = (__half*)Sr;
        float* dst = attn + ((size_t)bh * SEQ + qt) * SEQ;
        for (int j = l; j < region; j += 32) {
            float p = (j <= qt) ? Sr[j] * inv : 0.f;
            dst[j] = p;
            Pr[j] = __float2half(p);
        }
        for (int j = region + l; j < SEQ; j += 32) dst[j] = 0.f;
    }
    __syncthreads();

    // ---- AV ----
    const int wn2 = (wid >> 1) * 16;
    const __half* Ph = (const __half*)S;
    float oacc[2][4];
#pragma unroll
    for (int in = 0; in < 2; in++)
#pragma unroll
        for (int c = 0; c < 4; c++) oacc[in][c] = 0.f;

    for (int t = 0; t < ntile; t++) {
        if (t + 1 < ntile) {
            __half* KB = ((t + 1) & 1) ? KV1 : KV0;
            size_t goff = 2048 + (size_t)((t + 1) << 7) * 3072;
            LOAD_KV_TILE(KB, goff);
            asm volatile("cp.async.wait_group 1;" ::: "memory");
        } else {
            asm volatile("cp.async.wait_group 0;" ::: "memory");
        }
        __syncthreads();
        const __half* KB = (t & 1) ? KV1 : KV0;
#pragma unroll
        for (int u = 0; u < 16; u++) {
            int i = tid + 256 * u;
            int s2 = i & 31, tok = i >> 5;
            __half2 v = *(const __half2*)&KB[tok * KVP + s2 * 2];
            Vt[(s2 * 2) * VTP + tok]     = __low2half(v);
            Vt[(s2 * 2 + 1) * VTP + tok] = __high2half(v);
        }
        __syncthreads();
        int kt0 = t << 7;
#pragma unroll
        for (int kk = 0; kk < 8; kk++) {
            int k0 = kk * 16;
            uint32_t a0 = *(const uint32_t*)&Ph[(wm + lq) * (SPITCH * 2) + kt0 + k0 + c2];
            uint32_t a1 = *(const uint32_t*)&Ph[(wm + lq + 8) * (SPITCH * 2) + kt0 + k0 + c2];
            uint32_t a2 = *(const uint32_t*)&Ph[(wm + lq) * (SPITCH * 2) + kt0 + k0 + c2 + 8];
            uint32_t a3 = *(const uint32_t*)&Ph[(wm + lq + 8) * (SPITCH * 2) + kt0 + k0 + c2 + 8];
#pragma unroll
            for (int in = 0; in < 2; in++) {
                int s = wn2 + in * 8 + lq;
                uint32_t b0 = *(const uint32_t*)&Vt[s * VTP + k0 + c2];
                uint32_t b1 = *(const uint32_t*)&Vt[s * VTP + k0 + c2 + 8];
                hmma(oacc[in], a0, a1, a2, a3, b0, b1);
            }
        }
        __syncthreads();
    }
#pragma unroll
    for (int in = 0; in < 2; in++) {
        int q = q0 + wm + lq;
        int s = wn2 + in * 8 + c2;
        *(__half2*)&oh[(size_t)(b * SEQ + q) * DIM + hh * 64 + s] =
            __halves2half2(__float2half(oacc[in][0]), __float2half(oacc[in][1]));
        *(__half2*)&oh[(size_t)(b * SEQ + q + 8) * DIM + hh * 64 + s] =
            __halves2half2(__float2half(oacc[in][2]), __float2half(oacc[in][3]));
    }
}
#undef LOAD_KV_TILE

// ---------------------------------------------------------------------------
// Merge per-slab (m,s) partials -> per-row loss
// ---------------------------------------------------------------------------
__global__ __launch_bounds__(256)
void loss_from_parts(const float2* __restrict__ part, const float* __restrict__ zt,
                     float* __restrict__ rowloss)
{
    int w = threadIdx.x >> 5, l = threadIdx.x & 31;
    int row = blockIdx.x * 8 + w;
    float m = -INFINITY, s = 0.f;
    for (int p = l; p < NSLAB; p += 32) {
        float2 ps = part[(size_t)row * NSLAB + p];
        float M = fmaxf(m, ps.x);
        s = s * __expf(m - M) + ps.y * __expf(ps.x - M);
        m = M;
    }
#pragma unroll
    for (int st = 16; st > 0; st >>= 1) {
        float m2 = __shfl_xor_sync(0xFFFFFFFF, m, st);
        float s2 = __shfl_xor_sync(0xFFFFFFFF, s, st);
        float M = fmaxf(m, m2);
        s = s * __expf(m - M) + s2 * __expf(m2 - M);
        m = M;
    }
    if (l == 0) rowloss[row] = m + logf(s) - zt[row];
}

__global__ void loss_reduce_kernel(const float* __restrict__ rowloss, float* __restrict__ out)
{
    __shared__ float red[256];
    int tid = threadIdx.x;
    float s = 0.f;
    for (int i = tid; i < ROWS; i += 256) s += rowloss[i];
    red[tid] = s;
    __syncthreads();
    for (int st = 128; st > 0; st >>= 1) {
        if (tid < st) red[tid] += red[tid + st];
        __syncthreads();
    }
    if (tid == 0) out[0] = red[0] * (1.0f / ROWS);
}

// ---------------------------------------------------------------------------
// Host
// ---------------------------------------------------------------------------
extern "C" void kernel_launch(void* const* d_in, const int* in_sizes, int n_in,
                              void* d_out, int out_size)
{
    const int*   idx     = (const int*)  d_in[0];
    const int*   targets = (const int*)  d_in[1];
    const float* tok_emb = (const float*)d_in[2];
    const float* pos_emb = (const float*)d_in[3];
    const float* ln1_g   = (const float*)d_in[4];
    const float* ln1_b   = (const float*)d_in[5];
    const float* Wq      = (const float*)d_in[6];
    const float* Wk      = (const float*)d_in[7];
    const float* Wv      = (const float*)d_in[8];
    const float* Wp      = (const float*)d_in[9];
    const float* bp      = (const float*)d_in[10];
    const float* ln2_g   = (const float*)d_in[11];
    const float* ln2_b   = (const float*)d_in[12];
    const float* W1      = (const float*)d_in[13];
    const float* b1      = (const float*)d_in[14];
    const float* W2      = (const float*)d_in[15];
    const float* b2      = (const float*)d_in[16];
    const float* lnf_g   = (const float*)d_in[17];
    const float* lnf_b   = (const float*)d_in[18];
    const float* Wlm     = (const float*)d_in[19];
    const float* blm     = (const float*)d_in[20];

    float* out      = (float*)d_out;
    float* attn_out = out + 1;

    float *x, *rl, *ztp;
    float2* part;
    __half *hbuf, *qkvh, *ohb, *ffh, *wth;
    cudaGetSymbolAddress((void**)&x,    g_x);
    cudaGetSymbolAddress((void**)&hbuf, g_hh);
    cudaGetSymbolAddress((void**)&qkvh, g_qkvh);
    cudaGetSymbolAddress((void**)&ohb,  g_oh);
    cudaGetSymbolAddress((void**)&ffh,  g_ffh);
    cudaGetSymbolAddress((void**)&wth,  g_wth);
    cudaGetSymbolAddress((void**)&part, g_part);
    cudaGetSymbolAddress((void**)&ztp,  g_zt);
    cudaGetSymbolAddress((void**)&rl,   g_rl);

    cudaFuncSetAttribute(gemm_mma<0>, cudaFuncAttributeMaxDynamicSharedMemorySize, GEMM_SMEM);
    cudaFuncSetAttribute(gemm_mma<1>, cudaFuncAttributeMaxDynamicSharedMemorySize, GEMM_SMEM);
    cudaFuncSetAttribute(gemm_mma<2>, cudaFuncAttributeMaxDynamicSharedMemorySize, GEMM_SMEM);
    cudaFuncSetAttribute(gemm_mma<3>, cudaFuncAttributeMaxDynamicSharedMemorySize, GEMM_SMEM);
    cudaFuncSetAttribute(gemm_lm,     cudaFuncAttributeMaxDynamicSharedMemorySize, GEMM_SMEM);
    cudaFuncSetAttribute(attn_hmma,   cudaFuncAttributeMaxDynamicSharedMemorySize, ATT_SMEM);

    embed_kernel<<<ROWS, 256>>>(idx, tok_emb, pos_emb, x);

    for (int l = 0; l < NL; l++) {
        ln_kernel<<<ROWS, 256>>>(x, ln1_g + (size_t)l * DIM, ln1_b + (size_t)l * DIM, hbuf);
        pack_qkv_t<<<dim3(3 * DIM, DIM / 256), 256>>>(Wq, Wk, Wv, wth, l);
        gemm_mma<3><<<dim3(3 * DIM / 128, ROWS / 128), 256, GEMM_SMEM>>>(
            hbuf, wth, nullptr, nullptr, qkvh, 3 * DIM, DIM);

        float* attnL = attn_out + (size_t)l * BATCH * NH * SEQ * SEQ;
        attn_hmma<<<dim3(SEQ / SQ, BATCH * NH), 256, ATT_SMEM>>>(qkvh, attnL, ohb);

        transpose_k<<<dim3(DIM / 32, DIM / 32), dim3(32, 8)>>>(
            Wp + (size_t)l * DIM * DIM, wth, DIM, DIM);
        gemm_mma<1><<<dim3(DIM / 128, ROWS / 128), 256, GEMM_SMEM>>>(
            ohb, wth, bp + (size_t)l * DIM, x, x, DIM, DIM);

        ln_kernel<<<ROWS, 256>>>(x, ln2_g + (size_t)l * DIM, ln2_b + (size_t)l * DIM, hbuf);

        transpose_k<<<dim3(FFD / 32, DIM / 32), dim3(32, 8)>>>(
            W1 + (size_t)l * DIM * FFD, wth, DIM, FFD);
        gemm_mma<2><<<dim3(FFD / 128, ROWS / 128), 256, GEMM_SMEM>>>(
            hbuf, wth, b1 + (size_t)l * FFD, nullptr, ffh, FFD, DIM);

        transpose_k<<<dim3(DIM / 32, FFD / 32), dim3(32, 8)>>>(
            W2 + (size_t)l * FFD * DIM, wth, FFD, DIM);
        gemm_mma<1><<<dim3(DIM / 128, ROWS / 128), 256, GEMM_SMEM>>>(
            ffh, wth, b2 + (size_t)l * DIM, x, x, DIM, FFD);
    }

    ln_kernel<<<ROWS, 256>>>(x, lnf_g, lnf_b, hbuf);
    transpose_k<<<dim3(VOCAB / 32, DIM / 32), dim3(32, 8)>>>(Wlm, wth, DIM, VOCAB);
    gemm_lm<<<dim3(NSLAB, ROWS / 128), 256, GEMM_SMEM>>>(
        hbuf, wth, blm, targets, part, ztp, DIM);

    loss_from_parts<<<ROWS / 8, 256>>>(part, ztp, rl);
    loss_reduce_kernel<<<1, 256>>>(rl, out);
}

// round 11
// speedup vs baseline: 9.6062x; 1.2055x over previous
#include <cuda_runtime.h>
#include <cuda_fp16.h>
#include <math.h>
#include <stdint.h>

#define BATCH 4
#define SEQ   1024
#define DIM   1024
#define NH    16
#define HS    64
#define NL    4
#define FFD   4096
#define VOCAB 32000
#define ROWS  (BATCH * SEQ)
#define NSLAB (VOCAB / 128)            // 250

// ---------------------------------------------------------------------------
// Scratch
// ---------------------------------------------------------------------------
__device__ float  g_x   [(size_t)ROWS * DIM];        // residual (fp32)
__device__ __half g_hh  [(size_t)ROWS * DIM];        // LN output (fp16)
__device__ __half g_qkvh[(size_t)ROWS * 3 * DIM];    // q|k|v per row (fp16)
__device__ __half g_oh  [(size_t)ROWS * DIM];        // attn output (fp16)
__device__ __half g_ffh [(size_t)ROWS * FFD];        // MLP hidden (fp16)
__device__ __half g_wth [(size_t)VOCAB * DIM];       // transposed weights (fp16)
__device__ float2 g_part[(size_t)ROWS * NSLAB];      // per-slab (max, sumexp)
__device__ float  g_zt  [ROWS];                      // target logits
__device__ float  g_rl  [ROWS];

// ---------------------------------------------------------------------------
// Helpers
// ---------------------------------------------------------------------------
__device__ __forceinline__ uint32_t s2u(const void* p) {
    uint32_t a;
    asm("{ .reg .u64 t; cvta.to.shared.u64 t, %1; cvt.u32.u64 %0, t; }" : "=r"(a) : "l"(p));
    return a;
}
__device__ __forceinline__ void cpa16(uint32_t dst, const void* src) {
    asm volatile("cp.async.cg.shared.global [%0], [%1], 16;" :: "r"(dst), "l"(src));
}
__device__ __forceinline__ void hmma(float* c, uint32_t a0, uint32_t a1, uint32_t a2,
                                     uint32_t a3, uint32_t b0, uint32_t b1) {
    asm volatile(
        "mma.sync.aligned.m16n8k16.row.col.f32.f16.f16.f32 "
        "{%0,%1,%2,%3}, {%4,%5,%6,%7}, {%8,%9}, {%0,%1,%2,%3};"
        : "+f"(c[0]), "+f"(c[1]), "+f"(c[2]), "+f"(c[3])
        : "r"(a0), "r"(a1), "r"(a2), "r"(a3), "r"(b0), "r"(b1));
}
__device__ __forceinline__ void ldsm4(uint32_t* d, uint32_t addr) {
    asm volatile("ldmatrix.sync.aligned.m8n8.x4.shared.b16 {%0,%1,%2,%3}, [%4];"
                 : "=r"(d[0]), "=r"(d[1]), "=r"(d[2]), "=r"(d[3]) : "r"(addr));
}
// e^x for x <= 0, FFMA/ALU-pipe polynomial (relieves MUFU)
__device__ __forceinline__ float exp_poly(float x) {
    float z = x * 1.4426950408889634f;
    float t = z + 12582912.0f;
    float n = t - 12582912.0f;
    float f = z - n;
    float p = 1.3333558e-3f;
    p = fmaf(p, f, 9.6181291e-3f);
    p = fmaf(p, f, 5.5504109e-2f);
    p = fmaf(p, f, 2.4022651e-1f);
    p = fmaf(p, f, 6.9314718e-1f);
    p = fmaf(p, f, 1.0f);
    float sc = __int_as_float((((int)n) + 127) << 23);
    return (x < -80.f) ? 0.f : p * sc;
}

// ---------------------------------------------------------------------------
// Embedding
// ---------------------------------------------------------------------------
__global__ void embed_kernel(const int* __restrict__ idx,
                             const float* __restrict__ tok,
                             const float* __restrict__ pos,
                             float* __restrict__ x)
{
    int row = blockIdx.x;
    int t   = row & (SEQ - 1);
    int tk  = idx[row];
    const float* te = tok + (size_t)tk * DIM;
    const float* pe = pos + (size_t)t * DIM;
    float* xr = x + (size_t)row * DIM;
    for (int i = threadIdx.x; i < DIM; i += blockDim.x)
        xr[i] = te[i] + pe[i];
}

// ---------------------------------------------------------------------------
// LayerNorm -> fp16, warp-per-row (8 rows per 256-thread CTA)
// ---------------------------------------------------------------------------
__global__ __launch_bounds__(256)
void ln_kernel(const float* __restrict__ x,
               const float* __restrict__ g,
               const float* __restrict__ b,
               __half* __restrict__ y)
{
    int w = threadIdx.x >> 5, l = threadIdx.x & 31;
    int row = blockIdx.x * 8 + w;
    const float4* xr = (const float4*)(x + (size_t)row * DIM);
    float4 v[8];
    float s = 0.f, ss = 0.f;
#pragma unroll
    for (int j = 0; j < 8; j++) {
        v[j] = xr[l + 32 * j];
        s  += v[j].x + v[j].y + v[j].z + v[j].w;
        ss += v[j].x * v[j].x + v[j].y * v[j].y + v[j].z * v[j].z + v[j].w * v[j].w;
    }
#pragma unroll
    for (int st = 16; st > 0; st >>= 1) {
        s  += __shfl_xor_sync(0xFFFFFFFF, s, st);
        ss += __shfl_xor_sync(0xFFFFFFFF, ss, st);
    }
    float mean = s * (1.0f / DIM);
    float var  = fmaxf(ss * (1.0f / DIM) - mean * mean, 0.f);
    float rstd = rsqrtf(var + 1e-5f);
    const float4* g4 = (const float4*)g;
    const float4* b4 = (const float4*)b;
    __half2* yr = (__half2*)(y + (size_t)row * DIM);
#pragma unroll
    for (int j = 0; j < 8; j++) {
        int i4 = l + 32 * j;
        float4 gg = g4[i4], bb = b4[i4];
        float o0 = (v[j].x - mean) * rstd * gg.x + bb.x;
        float o1 = (v[j].y - mean) * rstd * gg.y + bb.y;
        float o2 = (v[j].z - mean) * rstd * gg.z + bb.z;
        float o3 = (v[j].w - mean) * rstd * gg.w + bb.w;
        yr[i4 * 2]     = __halves2half2(__float2half(o0), __float2half(o1));
        yr[i4 * 2 + 1] = __halves2half2(__float2half(o2), __float2half(o3));
    }
}

// ---------------------------------------------------------------------------
// Pack Wq|Wk|Wv -> [3*DIM][DIM] K-major fp16, coalesced via smem tile.
// grid (HS/32, DIM/32, 3*NH), block (32,8)
// ---------------------------------------------------------------------------
__global__ void pack_qkv_t(const float* __restrict__ Wq,
                           const float* __restrict__ Wk,
                           const float* __restrict__ Wv,
                           __half* __restrict__ out, int l)
{
    __shared__ float t[32][33];
    int z = blockIdx.z;                    // which*16 + h
    int which = z >> 4, h = z & 15;
    int s0 = blockIdx.x * 32, d0 = blockIdx.y * 32;
    int x = threadIdx.x, y = threadIdx.y;
    const float* W = (which == 0) ? Wq : (which == 1) ? Wk : Wv;
    const float* base = W + ((size_t)l * NH + h) * DIM * HS;     // [DIM][HS]
#pragma unroll
    for (int j = 0; j < 4; j++)
        t[y + 8 * j][x] = base[(size_t)(d0 + y + 8 * j) * HS + s0 + x];
    __syncthreads();
    __half* o = out + (size_t)(which * 1024 + h * 64) * DIM;
#pragma unroll
    for (int j = 0; j < 4; j++)
        o[(size_t)(s0 + y + 8 * j) * DIM + d0 + x] = __float2half(t[x][y + 8 * j]);
}

// ---------------------------------------------------------------------------
// Transpose [R][C] fp32 -> [C][R] fp16
// ---------------------------------------------------------------------------
__global__ void transpose_k(const float* __restrict__ in, __half* __restrict__ out,
                            int R, int C)
{
    __shared__ float t[32][33];
    int c0 = blockIdx.x * 32, r0 = blockIdx.y * 32;
    int x = threadIdx.x, y = threadIdx.y;
#pragma unroll
    for (int j = 0; j < 4; j++)
        t[y + 8 * j][x] = in[(size_t)(r0 + y + 8 * j) * C + c0 + x];
    __syncthreads();
#pragma unroll
    for (int j = 0; j < 4; j++)
        out[(size_t)(c0 + y + 8 * j) * R + r0 + x] = __float2half(t[x][y + 8 * j]);
}

// ---------------------------------------------------------------------------
// fp16 HMMA GEMM: BK=64, XOR-swizzled smem (no pad), ldmatrix fragments,
// 3-stage cp.async pipeline, one __syncthreads per tile.
// C[M x N] = A[M x K] @ Bt[N x K]^T
// EPI: 0 = f32 +bias | 1 = f32 +bias+res | 2 = fp16 relu(+bias) | 3 = fp16
// ---------------------------------------------------------------------------
#define BK 64
#define TILEB (128 * BK * 2)           // 16384 B per operand tile
#define GEMM_SMEM (6 * TILEB)          // 3 stages x (A,B) = 96 KB

#define GEMM_PRE()                                                            \
    extern __shared__ __half smh[];                                           \
    uint32_t sA = s2u(smh);                                                   \
    uint32_t sB = sA + 3 * TILEB;                                             \
    const int tid = threadIdx.x;                                              \
    const int bn = blockIdx.x * 128;                                          \
    const int bm = blockIdx.y * 128;                                          \
    const int wid = tid >> 5, l = tid & 31;                                   \
    const int wm = (wid & 1) * 64;                                            \
    const int wn = (wid >> 1) * 32;                                           \
    const int nt = K / BK;                                                    \
    const int c2 = (l & 3) * 2;                                               \
    const int lq = l >> 2;                                                    \
    const int ldr = tid >> 3;              /* 0..31 */                        \
    const int ldc8 = tid & 7;              /* chunk col */                    \
    const __half* Ag = A  + (size_t)(bm + ldr) * K + ldc8 * 8;                \
    const __half* Bg = Bt + (size_t)(bn + ldr) * K + ldc8 * 8;                \
    const uint32_t sAo = sA + (ldr * BK + ((ldc8 ^ (ldr & 7)) * 8)) * 2;      \
    const uint32_t sBo = sB + (ldr * BK + ((ldc8 ^ (ldr & 7)) * 8)) * 2;      \
    float acc[4][4][4];                                                       \
    _Pragma("unroll")                                                         \
    for (int i = 0; i < 4; i++)                                               \
        _Pragma("unroll")                                                     \
        for (int j = 0; j < 4; j++)                                           \
            _Pragma("unroll")                                                 \
            for (int c = 0; c < 4; c++) acc[i][j][c] = 0.f;                   \
    const int a_row  = l & 15;                                                \
    const int a_kch  = l >> 4;             /* chunk 0/1 within kk */          \
    const int b_nrow = (l & 7) + ((l >> 4) << 3);                             \
    const int b_kch  = (l >> 3) & 1;

#define LOAD_TILE(T)                                                          \
    {                                                                         \
        int buf_ = (T) % 3;                                                   \
        int ko_ = (T) * BK;                                                   \
        _Pragma("unroll")                                                     \
        for (int p = 0; p < 4; p++) {                                         \
            cpa16(sAo + buf_ * TILEB + p * 32 * BK * 2,                       \
                  Ag + (size_t)(p * 32) * K + ko_);                           \
            cpa16(sBo + buf_ * TILEB + p * 32 * BK * 2,                       \
                  Bg + (size_t)(p * 32) * K + ko_);                           \
        }                                                                     \
        asm volatile("cp.async.commit_group;" ::: "memory");                  \
    }

#define GEMM_MAINLOOP()                                                       \
    LOAD_TILE(0);                                                             \
    if (nt > 1) LOAD_TILE(1);                                                 \
    for (int t = 0; t < nt; t++) {                                            \
        if (t + 1 < nt) { asm volatile("cp.async.wait_group 1;" ::: "memory"); } \
        else            { asm volatile("cp.async.wait_group 0;" ::: "memory"); } \
        __syncthreads();                                                      \
        if (t + 2 < nt) LOAD_TILE(t + 2);                                     \
        uint32_t Ab = sA + (t % 3) * TILEB;                                   \
        uint32_t Bb = sB + (t % 3) * TILEB;                                   \
        _Pragma("unroll")                                                     \
        for (int kk = 0; kk < 4; kk++) {                                      \
            uint32_t a[4][4], bfr[2][4];                                      \
            _Pragma("unroll")                                                 \
            for (int im = 0; im < 4; im++) {                                  \
                int row_ = wm + im * 16 + a_row;                              \
                int ch_ = (kk * 2 + a_kch) ^ (row_ & 7);                      \
                ldsm4(a[im], Ab + (row_ * BK + ch_ * 8) * 2);                 \
            }                                                                 \
            _Pragma("unroll")                                                 \
            for (int g = 0; g < 2; g++) {                                     \
                int row_ = wn + g * 16 + b_nrow;                              \
                int ch_ = (kk * 2 + b_kch) ^ (row_ & 7);                      \
                ldsm4(bfr[g], Bb + (row_ * BK + ch_ * 8) * 2);                \
            }                                                                 \
            _Pragma("unroll")                                                 \
            for (int im = 0; im < 4; im++)                                    \
                _Pragma("unroll")                                             \
                for (int in = 0; in < 4; in++)                                \
                    hmma(acc[im][in], a[im][0], a[im][1], a[im][2], a[im][3], \
                         bfr[in >> 1][(in & 1) * 2], bfr[in >> 1][(in & 1) * 2 + 1]); \
        }                                                                     \
    }

template <int EPI>
__global__ __launch_bounds__(256, 2)
void gemm_mma(const __half* __restrict__ A, const __half* __restrict__ Bt,
              const float* __restrict__ bias, const float* __restrict__ res,
              void* __restrict__ Cv, int N, int K)
{
    GEMM_PRE();
    GEMM_MAINLOOP();

    float*  Cf = (float*)Cv;
    __half* Ch = (__half*)Cv;
#pragma unroll
    for (int im = 0; im < 4; im++) {
        int r0 = bm + wm + im * 16 + lq;
#pragma unroll
        for (int in = 0; in < 4; in++) {
            int cc = bn + wn + in * 8 + c2;
            float b0 = 0.f, b1 = 0.f;
            if (bias) { b0 = bias[cc]; b1 = bias[cc + 1]; }
            float v0 = acc[im][in][0] + b0;
            float v1 = acc[im][in][1] + b1;
            float v2 = acc[im][in][2] + b0;
            float v3 = acc[im][in][3] + b1;
            if (EPI == 1) {
                v0 += res[(size_t)r0 * N + cc];
                v1 += res[(size_t)r0 * N + cc + 1];
                v2 += res[(size_t)(r0 + 8) * N + cc];
                v3 += res[(size_t)(r0 + 8) * N + cc + 1];
            }
            if (EPI == 2 || EPI == 3) {
                if (EPI == 2) {
                    v0 = fmaxf(v0, 0.f); v1 = fmaxf(v1, 0.f);
                    v2 = fmaxf(v2, 0.f); v3 = fmaxf(v3, 0.f);
                }
                *(__half2*)&Ch[(size_t)r0 * N + cc] =
                    __halves2half2(__float2half(v0), __float2half(v1));
                *(__half2*)&Ch[(size_t)(r0 + 8) * N + cc] =
                    __halves2half2(__float2half(v2), __float2half(v3));
            } else {
                *(float2*)&Cf[(size_t)r0 * N + cc] = make_float2(v0, v1);
                *(float2*)&Cf[(size_t)(r0 + 8) * N + cc] = make_float2(v2, v3);
            }
        }
    }
}

// ---------------------------------------------------------------------------
// LM-head GEMM with fused logsumexp partials + target-logit capture.
// ---------------------------------------------------------------------------
__global__ __launch_bounds__(256, 2)
void gemm_lm(const __half* __restrict__ A, const __half* __restrict__ Bt,
             const float* __restrict__ bias, const int* __restrict__ targets,
             float2* __restrict__ part, float* __restrict__ zt, int K)
{
    GEMM_PRE();
    GEMM_MAINLOOP();

#pragma unroll
    for (int im = 0; im < 4; im++) {
        int r0g = bm + wm + im * 16 + lq;
        int r1g = r0g + 8;
        int t0 = targets[r0g], t1 = targets[r1g];
#pragma unroll
        for (int in = 0; in < 4; in++) {
            int cc = bn + wn + in * 8 + c2;
            float b0 = bias[cc], b1 = bias[cc + 1];
            acc[im][in][0] += b0; acc[im][in][1] += b1;
            acc[im][in][2] += b0; acc[im][in][3] += b1;
            if (cc     == t0) zt[r0g] = acc[im][in][0];
            if (cc + 1 == t0) zt[r0g] = acc[im][in][1];
            if (cc     == t1) zt[r1g] = acc[im][in][2];
            if (cc + 1 == t1) zt[r1g] = acc[im][in][3];
        }
    }

    float* redM = (float*)smh;             // [128][4]
    float* redS = redM + 512;
    __syncthreads();

#pragma unroll
    for (int im = 0; im < 4; im++)
#pragma unroll
        for (int h = 0; h < 2; h++) {
            float mx = -INFINITY;
#pragma unroll
            for (int in = 0; in < 4; in++)
                mx = fmaxf(mx, fmaxf(acc[im][in][h * 2], acc[im][in][h * 2 + 1]));
            mx = fmaxf(mx, __shfl_xor_sync(0xFFFFFFFF, mx, 1));
            mx = fmaxf(mx, __shfl_xor_sync(0xFFFFFFFF, mx, 2));
            int row = wm + im * 16 + lq + h * 8;
            if ((l & 3) == 0) redM[row * 4 + (wid >> 1)] = mx;
        }
    __syncthreads();

#pragma unroll
    for (int im = 0; im < 4; im++)
#pragma unroll
        for (int h = 0; h < 2; h++) {
            int row = wm + im * 16 + lq + h * 8;
            float rm = fmaxf(fmaxf(redM[row * 4 + 0], redM[row * 4 + 1]),
                             fmaxf(redM[row * 4 + 2], redM[row * 4 + 3]));
            float se = 0.f;
#pragma unroll
            for (int in = 0; in < 4; in++) {
                float d0 = acc[im][in][h * 2]     - rm;
                float d1 = acc[im][in][h * 2 + 1] - rm;
                if (in & 1) { se += exp_poly(d0); se += exp_poly(d1); }
                else        { se += __expf(d0);   se += __expf(d1);   }
            }
            se += __shfl_xor_sync(0xFFFFFFFF, se, 1);
            se += __shfl_xor_sync(0xFFFFFFFF, se, 2);
            if ((l & 3) == 0) redS[row * 4 + (wid >> 1)] = se;
        }
    __syncthreads();

    if (tid < 128) {
        float m = fmaxf(fmaxf(redM[tid * 4 + 0], redM[tid * 4 + 1]),
                        fmaxf(redM[tid * 4 + 2], redM[tid * 4 + 3]));
        float s = redS[tid * 4 + 0] + redS[tid * 4 + 1]
                + redS[tid * 4 + 2] + redS[tid * 4 + 3];
        part[(size_t)(bm + tid) * NSLAB + blockIdx.x] = make_float2(m, s);
    }
}

// ---------------------------------------------------------------------------
// HMMA attention: 32 q-rows x one (b,h) per CTA.
// ---------------------------------------------------------------------------
#define SQ 32
#define SPITCH 1032                    // floats per S row
#define KVP 72                         // halves per KV row
#define VTP 136                        // halves per Vt row
#define ATT_SMEM (SQ * SPITCH * 4 + 2 * 128 * KVP * 2 + 64 * VTP * 2 + SQ * KVP * 2)

#define LOAD_KV_TILE(DSTP, GOFF)                                              \
    {                                                                         \
        _Pragma("unroll")                                                     \
        for (int u_ = 0; u_ < 4; u_++) {                                      \
            int c_ = tid + 256 * u_;                                          \
            int tok_ = c_ >> 3, o8_ = (c_ & 7) * 8;                           \
            cpa16(s2u(DSTP) + (tok_ * KVP + o8_) * 2,                         \
                  qkvh + qbase + (GOFF) + (size_t)tok_ * 3072 + o8_);         \
        }                                                                     \
        asm volatile("cp.async.commit_group;" ::: "memory");                  \
    }

__global__ __launch_bounds__(256)
void attn_hmma(const __half* __restrict__ qkvh, float* __restrict__ attn,
               __half* __restrict__ oh)
{
    extern __shared__ float sm[];
    float*  S   = sm;                                  // [32][1032] f32
    __half* KV0 = (__half*)(sm + SQ * SPITCH);         // [128][72]
    __half* KV1 = KV0 + 128 * KVP;
    __half* Vt  = KV1 + 128 * KVP;                     // [64][136]
    __half* Q   = Vt + 64 * VTP;                       // [32][72]

    const int tid = threadIdx.x;
    const int q0 = blockIdx.x * SQ;
    const int bh = blockIdx.y;
    const int b = bh >> 4, hh = bh & 15;
    const int wid = tid >> 5, l = tid & 31;
    const int c2 = (l & 3) * 2;
    const int lq = l >> 2;
    const int ntile = (q0 >> 7) + 1;
    const int region = ntile << 7;
    const size_t qbase = (size_t)(b * SEQ) * 3072 + hh * 64;

    {
        int r = tid >> 3, c8 = (tid & 7) * 8;
        cpa16(s2u(Q) + (r * KVP + c8) * 2, qkvh + qbase + (size_t)(q0 + r) * 3072 + c8);
    }
    LOAD_KV_TILE(KV0, 1024);

    const int wm = (wid & 1) * 16;
    const int wn = (wid >> 1) * 32;

    // ---- scores ----
    for (int t = 0; t < ntile; t++) {
        if (t + 1 < ntile) {
            __half* KB = ((t + 1) & 1) ? KV1 : KV0;
            size_t goff = 1024 + (size_t)((t + 1) << 7) * 3072;
            LOAD_KV_TILE(KB, goff);
            asm volatile("cp.async.wait_group 1;" ::: "memory");
        } else {
            asm volatile("cp.async.wait_group 0;" ::: "memory");
        }
        __syncthreads();
        const __half* KB = (t & 1) ? KV1 : KV0;
        int kt0 = t << 7;
        float acc[4][4];
#pragma unroll
        for (int in = 0; in < 4; in++)
#pragma unroll
            for (int c = 0; c < 4; c++) acc[in][c] = 0.f;
#pragma unroll
        for (int kk = 0; kk < 4; kk++) {
            int k0 = kk * 16;
            uint32_t a0 = *(const uint32_t*)&Q[(wm + lq) * KVP + k0 + c2];
            uint32_t a1 = *(const uint32_t*)&Q[(wm + lq + 8) * KVP + k0 + c2];
            uint32_t a2 = *(const uint32_t*)&Q[(wm + lq) * KVP + k0 + c2 + 8];
            uint32_t a3 = *(const uint32_t*)&Q[(wm + lq + 8) * KVP + k0 + c2 + 8];
#pragma unroll
            for (int in = 0; in < 4; in++) {
                int n = wn + in * 8 + lq;
                uint32_t b0 = *(const uint32_t*)&KB[n * KVP + k0 + c2];
                uint32_t b1 = *(const uint32_t*)&KB[n * KVP + k0 + c2 + 8];
                hmma(acc[in], a0, a1, a2, a3, b0, b1);
            }
        }
        int qr = wm + lq;
#pragma unroll
        for (int in = 0; in < 4; in++) {
            int kg = kt0 + wn + in * 8 + c2;
            float v0 = (kg     <= q0 + qr)     ? acc[in][0] * 0.125f : -INFINITY;
            float v1 = (kg + 1 <= q0 + qr)     ? acc[in][1] * 0.125f : -INFINITY;
            float v2 = (kg     <= q0 + qr + 8) ? acc[in][2] * 0.125f : -INFINITY;
            float v3 = (kg + 1 <= q0 + qr + 8) ? acc[in][3] * 0.125f : -INFINITY;
            *(float2*)&S[qr * SPITCH + kg]       = make_float2(v0, v1);
            *(float2*)&S[(qr + 8) * SPITCH + kg] = make_float2(v2, v3);
        }
        __syncthreads();
    }

    // prefetch V tile 0 (overlaps softmax)
    LOAD_KV_TILE(KV0, 2048);

    // ---- softmax ----
    for (int rr = 0; rr < 4; rr++) {
        int q = wid * 4 + rr;
        int qt = q0 + q;
        float* Sr = S + q * SPITCH;
        float m = -INFINITY;
        for (int j = l; j <= qt; j += 32) m = fmaxf(m, Sr[j]);
#pragma unroll
        for (int st = 16; st > 0; st >>= 1)
            m = fmaxf(m, __shfl_xor_sync(0xFFFFFFFF, m, st));
        float ssum = 0.f;
        int it = 0;
        for (int j = l; j <= qt; j += 32, it++) {
            float d = Sr[j] - m;
            float e = (it & 1) ? exp_poly(d) : __expf(d);
            Sr[j] = e;
            ssum += e;
        }
#pragma unroll
        for (int st = 16; st > 0; st >>= 1)
            ssum += __shfl_xor_sync(0xFFFFFFFF, ssum, st);
        float inv = 1.0f / ssum;
        __half* Pr = (__half*)Sr;
        float* dst = attn + ((size_t)bh * SEQ + qt) * SEQ;
        for (int j = l; j < region; j += 32) {
            float p = (j <= qt) ? Sr[j] * inv : 0.f;
            dst[j] = p;
            Pr[j] = __float2half(p);
        }
        for (int j = region + l; j < SEQ; j += 32) dst[j] = 0.f;
    }
    __syncthreads();

    // ---- AV ----
    const int wn2 = (wid >> 1) * 16;
    const __half* Ph = (const __half*)S;
    float oacc[2][4];
#pragma unroll
    for (int in = 0; in < 2; in++)
#pragma unroll
        for (int c = 0; c < 4; c++) oacc[in][c] = 0.f;

    for (int t = 0; t < ntile; t++) {
        if (t + 1 < ntile) {
            __half* KB = ((t + 1) & 1) ? KV1 : KV0;
            size_t goff = 2048 + (size_t)((t + 1) << 7) * 3072;
            LOAD_KV_TILE(KB, goff);
            asm volatile("cp.async.wait_group 1;" ::: "memory");
        } else {
            asm volatile("cp.async.wait_group 0;" ::: "memory");
        }
        __syncthreads();
        const __half* KB = (t & 1) ? KV1 : KV0;
#pragma unroll
        for (int u = 0; u < 16; u++) {
            int i = tid + 256 * u;
            int s2 = i & 31, tok = i >> 5;
            __half2 v = *(const __half2*)&KB[tok * KVP + s2 * 2];
            Vt[(s2 * 2) * VTP + tok]     = __low2half(v);
            Vt[(s2 * 2 + 1) * VTP + tok] = __high2half(v);
        }
        __syncthreads();
        int kt0 = t << 7;
#pragma unroll
        for (int kk = 0; kk < 8; kk++) {
            int k0 = kk * 16;
            uint32_t a0 = *(const uint32_t*)&Ph[(wm + lq) * (SPITCH * 2) + kt0 + k0 + c2];
            uint32_t a1 = *(const uint32_t*)&Ph[(wm + lq + 8) * (SPITCH * 2) + kt0 + k0 + c2];
            uint32_t a2 = *(const uint32_t*)&Ph[(wm + lq) * (SPITCH * 2) + kt0 + k0 + c2 + 8];
            uint32_t a3 = *(const uint32_t*)&Ph[(wm + lq + 8) * (SPITCH * 2) + kt0 + k0 + c2 + 8];
#pragma unroll
            for (int in = 0; in < 2; in++) {
                int s = wn2 + in * 8 + lq;
                uint32_t b0 = *(const uint32_t*)&Vt[s * VTP + k0 + c2];
                uint32_t b1 = *(const uint32_t*)&Vt[s * VTP + k0 + c2 + 8];
                hmma(oacc[in], a0, a1, a2, a3, b0, b1);
            }
        }
        __syncthreads();
    }
#pragma unroll
    for (int in = 0; in < 2; in++) {
        int q = q0 + wm + lq;
        int s = wn2 + in * 8 + c2;
        *(__half2*)&oh[(size_t)(b * SEQ + q) * DIM + hh * 64 + s] =
            __halves2half2(__float2half(oacc[in][0]), __float2half(oacc[in][1]));
        *(__half2*)&oh[(size_t)(b * SEQ + q + 8) * DIM + hh * 64 + s] =
            __halves2half2(__float2half(oacc[in][2]), __float2half(oacc[in][3]));
    }
}
#undef LOAD_KV_TILE

// ---------------------------------------------------------------------------
// Merge per-slab (m,s) partials -> per-row loss
// ---------------------------------------------------------------------------
__global__ __launch_bounds__(256)
void loss_from_parts(const float2* __restrict__ part, const float* __restrict__ zt,
                     float* __restrict__ rowloss)
{
    int w = threadIdx.x >> 5, l = threadIdx.x & 31;
    int row = blockIdx.x * 8 + w;
    float m = -INFINITY, s = 0.f;
    for (int p = l; p < NSLAB; p += 32) {
        float2 ps = part[(size_t)row * NSLAB + p];
        float M = fmaxf(m, ps.x);
        s = s * __expf(m - M) + ps.y * __expf(ps.x - M);
        m = M;
    }
#pragma unroll
    for (int st = 16; st > 0; st >>= 1) {
        float m2 = __shfl_xor_sync(0xFFFFFFFF, m, st);
        float s2 = __shfl_xor_sync(0xFFFFFFFF, s, st);
        float M = fmaxf(m, m2);
        s = s * __expf(m - M) + s2 * __expf(m2 - M);
        m = M;
    }
    if (l == 0) rowloss[row] = m + logf(s) - zt[row];
}

__global__ void loss_reduce_kernel(const float* __restrict__ rowloss, float* __restrict__ out)
{
    __shared__ float red[256];
    int tid = threadIdx.x;
    float s = 0.f;
    for (int i = tid; i < ROWS; i += 256) s += rowloss[i];
    red[tid] = s;
    __syncthreads();
    for (int st = 128; st > 0; st >>= 1) {
        if (tid < st) red[tid] += red[tid + st];
        __syncthreads();
    }
    if (tid == 0) out[0] = red[0] * (1.0f / ROWS);
}

// ---------------------------------------------------------------------------
// Host
// ---------------------------------------------------------------------------
extern "C" void kernel_launch(void* const* d_in, const int* in_sizes, int n_in,
                              void* d_out, int out_size)
{
    const int*   idx     = (const int*)  d_in[0];
    const int*   targets = (const int*)  d_in[1];
    const float* tok_emb = (const float*)d_in[2];
    const float* pos_emb = (const float*)d_in[3];
    const float* ln1_g   = (const float*)d_in[4];
    const float* ln1_b   = (const float*)d_in[5];
    const float* Wq      = (const float*)d_in[6];
    const float* Wk      = (const float*)d_in[7];
    const float* Wv      = (const float*)d_in[8];
    const float* Wp      = (const float*)d_in[9];
    const float* bp      = (const float*)d_in[10];
    const float* ln2_g   = (const float*)d_in[11];
    const float* ln2_b   = (const float*)d_in[12];
    const float* W1      = (const float*)d_in[13];
    const float* b1      = (const float*)d_in[14];
    const float* W2      = (const float*)d_in[15];
    const float* b2      = (const float*)d_in[16];
    const float* lnf_g   = (const float*)d_in[17];
    const float* lnf_b   = (const float*)d_in[18];
    const float* Wlm     = (const float*)d_in[19];
    const float* blm     = (const float*)d_in[20];

    float* out      = (float*)d_out;
    float* attn_out = out + 1;

    float *x, *rl, *ztp;
    float2* part;
    __half *hbuf, *qkvh, *ohb, *ffh, *wth;
    cudaGetSymbolAddress((void**)&x,    g_x);
    cudaGetSymbolAddress((void**)&hbuf, g_hh);
    cudaGetSymbolAddress((void**)&qkvh, g_qkvh);
    cudaGetSymbolAddress((void**)&ohb,  g_oh);
    cudaGetSymbolAddress((void**)&ffh,  g_ffh);
    cudaGetSymbolAddress((void**)&wth,  g_wth);
    cudaGetSymbolAddress((void**)&part, g_part);
    cudaGetSymbolAddress((void**)&ztp,  g_zt);
    cudaGetSymbolAddress((void**)&rl,   g_rl);

    cudaFuncSetAttribute(gemm_mma<0>, cudaFuncAttributeMaxDynamicSharedMemorySize, GEMM_SMEM);
    cudaFuncSetAttribute(gemm_mma<1>, cudaFuncAttributeMaxDynamicSharedMemorySize, GEMM_SMEM);
    cudaFuncSetAttribute(gemm_mma<2>, cudaFuncAttributeMaxDynamicSharedMemorySize, GEMM_SMEM);
    cudaFuncSetAttribute(gemm_mma<3>, cudaFuncAttributeMaxDynamicSharedMemorySize, GEMM_SMEM);
    cudaFuncSetAttribute(gemm_lm,     cudaFuncAttributeMaxDynamicSharedMemorySize, GEMM_SMEM);
    cudaFuncSetAttribute(attn_hmma,   cudaFuncAttributeMaxDynamicSharedMemorySize, ATT_SMEM);

    embed_kernel<<<ROWS, 256>>>(idx, tok_emb, pos_emb, x);

    for (int l = 0; l < NL; l++) {
        ln_kernel<<<ROWS / 8, 256>>>(x, ln1_g + (size_t)l * DIM, ln1_b + (size_t)l * DIM, hbuf);
        pack_qkv_t<<<dim3(HS / 32, DIM / 32, 3 * NH), dim3(32, 8)>>>(Wq, Wk, Wv, wth, l);
        gemm_mma<3><<<dim3(3 * DIM / 128, ROWS / 128), 256, GEMM_SMEM>>>(
            hbuf, wth, nullptr, nullptr, qkvh, 3 * DIM, DIM);

        float* attnL = attn_out + (size_t)l * BATCH * NH * SEQ * SEQ;
        attn_hmma<<<dim3(SEQ / SQ, BATCH * NH), 256, ATT_SMEM>>>(qkvh, attnL, ohb);

        transpose_k<<<dim3(DIM / 32, DIM / 32), dim3(32, 8)>>>(
            Wp + (size_t)l * DIM * DIM, wth, DIM, DIM);
        gemm_mma<1><<<dim3(DIM / 128, ROWS / 128), 256, GEMM_SMEM>>>(
            ohb, wth, bp + (size_t)l * DIM, x, x, DIM, DIM);

        ln_kernel<<<ROWS / 8, 256>>>(x, ln2_g + (size_t)l * DIM, ln2_b + (size_t)l * DIM, hbuf);

        transpose_k<<<dim3(FFD / 32, DIM / 32), dim3(32, 8)>>>(
            W1 + (size_t)l * DIM * FFD, wth, DIM, FFD);
        gemm_mma<2><<<dim3(FFD / 128, ROWS / 128), 256, GEMM_SMEM>>>(
            hbuf, wth, b1 + (size_t)l * FFD, nullptr, ffh, FFD, DIM);

        transpose_k<<<dim3(DIM / 32, FFD / 32), dim3(32, 8)>>>(
            W2 + (size_t)l * FFD * DIM, wth, FFD, DIM);
        gemm_mma<1><<<dim3(DIM / 128, ROWS / 128), 256, GEMM_SMEM>>>(
            ffh, wth, b2 + (size_t)l * DIM, x, x, DIM, FFD);
    }

    ln_kernel<<<ROWS / 8, 256>>>(x, lnf_g, lnf_b, hbuf);
    transpose_k<<<dim3(VOCAB / 32, DIM / 32), dim3(32, 8)>>>(Wlm, wth, DIM, VOCAB);
    gemm_lm<<<dim3(NSLAB, ROWS / 128), 256, GEMM_SMEM>>>(
        hbuf, wth, blm, targets, part, ztp, DIM);

    loss_from_parts<<<ROWS / 8, 256>>>(part, ztp, rl);
    loss_reduce_kernel<<<1, 256>>>(rl, out);
}

// round 12
// speedup vs baseline: 10.7066x; 1.1146x over previous
#include <cuda_runtime.h>
#include <cuda_fp16.h>
#include <math.h>
#include <stdint.h>

#define BATCH 4
#define SEQ   1024
#define DIM   1024
#define NH    16
#define HS    64
#define NL    4
#define FFD   4096
#define VOCAB 32000
#define ROWS  (BATCH * SEQ)
#define NSLAB (VOCAB / 128)            // 250

// ---------------------------------------------------------------------------
// Scratch
// ---------------------------------------------------------------------------
__device__ float  g_x   [(size_t)ROWS * DIM];        // residual (fp32)
__device__ __half g_hh  [(size_t)ROWS * DIM];        // LN output (fp16)
__device__ __half g_qkvh[(size_t)ROWS * 3 * DIM];    // q|k|v per row (fp16)
__device__ __half g_oh  [(size_t)ROWS * DIM];        // attn output (fp16)
__device__ __half g_ffh [(size_t)ROWS * FFD];        // MLP hidden (fp16)
__device__ __half g_wth [(size_t)VOCAB * DIM];       // transposed weights (fp16)
__device__ float2 g_part[(size_t)ROWS * NSLAB];      // per-slab (max, sumexp)
__device__ float  g_zt  [ROWS];                      // target logits
__device__ float  g_rl  [ROWS];

// ---------------------------------------------------------------------------
// Helpers
// ---------------------------------------------------------------------------
__device__ __forceinline__ uint32_t s2u(const void* p) {
    uint32_t a;
    asm("{ .reg .u64 t; cvta.to.shared.u64 t, %1; cvt.u32.u64 %0, t; }" : "=r"(a) : "l"(p));
    return a;
}
__device__ __forceinline__ void cpa16(uint32_t dst, const void* src) {
    asm volatile("cp.async.cg.shared.global [%0], [%1], 16;" :: "r"(dst), "l"(src));
}
__device__ __forceinline__ void hmma(float* c, uint32_t a0, uint32_t a1, uint32_t a2,
                                     uint32_t a3, uint32_t b0, uint32_t b1) {
    asm volatile(
        "mma.sync.aligned.m16n8k16.row.col.f32.f16.f16.f32 "
        "{%0,%1,%2,%3}, {%4,%5,%6,%7}, {%8,%9}, {%0,%1,%2,%3};"
        : "+f"(c[0]), "+f"(c[1]), "+f"(c[2]), "+f"(c[3])
        : "r"(a0), "r"(a1), "r"(a2), "r"(a3), "r"(b0), "r"(b1));
}
__device__ __forceinline__ void ldsm4(uint32_t* d, uint32_t addr) {
    asm volatile("ldmatrix.sync.aligned.m8n8.x4.shared.b16 {%0,%1,%2,%3}, [%4];"
                 : "=r"(d[0]), "=r"(d[1]), "=r"(d[2]), "=r"(d[3]) : "r"(addr));
}
__device__ __forceinline__ void ldsm4t(uint32_t* d, uint32_t addr) {
    asm volatile("ldmatrix.sync.aligned.m8n8.x4.trans.shared.b16 {%0,%1,%2,%3}, [%4];"
                 : "=r"(d[0]), "=r"(d[1]), "=r"(d[2]), "=r"(d[3]) : "r"(addr));
}
// e^x for x <= 0, FFMA/ALU-pipe polynomial (relieves MUFU)
__device__ __forceinline__ float exp_poly(float x) {
    float z = x * 1.4426950408889634f;
    float t = z + 12582912.0f;
    float n = t - 12582912.0f;
    float f = z - n;
    float p = 1.3333558e-3f;
    p = fmaf(p, f, 9.6181291e-3f);
    p = fmaf(p, f, 5.5504109e-2f);
    p = fmaf(p, f, 2.4022651e-1f);
    p = fmaf(p, f, 6.9314718e-1f);
    p = fmaf(p, f, 1.0f);
    float sc = __int_as_float((((int)n) + 127) << 23);
    return (x < -80.f) ? 0.f : p * sc;
}

// ---------------------------------------------------------------------------
// Embedding
// ---------------------------------------------------------------------------
__global__ void embed_kernel(const int* __restrict__ idx,
                             const float* __restrict__ tok,
                             const float* __restrict__ pos,
                             float* __restrict__ x)
{
    int row = blockIdx.x;
    int t   = row & (SEQ - 1);
    int tk  = idx[row];
    const float* te = tok + (size_t)tk * DIM;
    const float* pe = pos + (size_t)t * DIM;
    float* xr = x + (size_t)row * DIM;
    for (int i = threadIdx.x; i < DIM; i += blockDim.x)
        xr[i] = te[i] + pe[i];
}

// ---------------------------------------------------------------------------
// LayerNorm -> fp16, warp-per-row (8 rows per 256-thread CTA)
// ---------------------------------------------------------------------------
__global__ __launch_bounds__(256)
void ln_kernel(const float* __restrict__ x,
               const float* __restrict__ g,
               const float* __restrict__ b,
               __half* __restrict__ y)
{
    int w = threadIdx.x >> 5, l = threadIdx.x & 31;
    int row = blockIdx.x * 8 + w;
    const float4* xr = (const float4*)(x + (size_t)row * DIM);
    float4 v[8];
    float s = 0.f, ss = 0.f;
#pragma unroll
    for (int j = 0; j < 8; j++) {
        v[j] = xr[l + 32 * j];
        s  += v[j].x + v[j].y + v[j].z + v[j].w;
        ss += v[j].x * v[j].x + v[j].y * v[j].y + v[j].z * v[j].z + v[j].w * v[j].w;
    }
#pragma unroll
    for (int st = 16; st > 0; st >>= 1) {
        s  += __shfl_xor_sync(0xFFFFFFFF, s, st);
        ss += __shfl_xor_sync(0xFFFFFFFF, ss, st);
    }
    float mean = s * (1.0f / DIM);
    float var  = fmaxf(ss * (1.0f / DIM) - mean * mean, 0.f);
    float rstd = rsqrtf(var + 1e-5f);
    const float4* g4 = (const float4*)g;
    const float4* b4 = (const float4*)b;
    __half2* yr = (__half2*)(y + (size_t)row * DIM);
#pragma unroll
    for (int j = 0; j < 8; j++) {
        int i4 = l + 32 * j;
        float4 gg = g4[i4], bb = b4[i4];
        float o0 = (v[j].x - mean) * rstd * gg.x + bb.x;
        float o1 = (v[j].y - mean) * rstd * gg.y + bb.y;
        float o2 = (v[j].z - mean) * rstd * gg.z + bb.z;
        float o3 = (v[j].w - mean) * rstd * gg.w + bb.w;
        yr[i4 * 2]     = __halves2half2(__float2half(o0), __float2half(o1));
        yr[i4 * 2 + 1] = __halves2half2(__float2half(o2), __float2half(o3));
    }
}

// ---------------------------------------------------------------------------
// Pack Wq|Wk|Wv -> [3*DIM][DIM] K-major fp16, coalesced via smem tile.
// ---------------------------------------------------------------------------
__global__ void pack_qkv_t(const float* __restrict__ Wq,
                           const float* __restrict__ Wk,
                           const float* __restrict__ Wv,
                           __half* __restrict__ out, int l)
{
    __shared__ float t[32][33];
    int z = blockIdx.z;                    // which*16 + h
    int which = z >> 4, h = z & 15;
    int s0 = blockIdx.x * 32, d0 = blockIdx.y * 32;
    int x = threadIdx.x, y = threadIdx.y;
    const float* W = (which == 0) ? Wq : (which == 1) ? Wk : Wv;
    const float* base = W + ((size_t)l * NH + h) * DIM * HS;     // [DIM][HS]
#pragma unroll
    for (int j = 0; j < 4; j++)
        t[y + 8 * j][x] = base[(size_t)(d0 + y + 8 * j) * HS + s0 + x];
    __syncthreads();
    __half* o = out + (size_t)(which * 1024 + h * 64) * DIM;
#pragma unroll
    for (int j = 0; j < 4; j++)
        o[(size_t)(s0 + y + 8 * j) * DIM + d0 + x] = __float2half(t[x][y + 8 * j]);
}

// ---------------------------------------------------------------------------
// Transpose [R][C] fp32 -> [C][R] fp16
// ---------------------------------------------------------------------------
__global__ void transpose_k(const float* __restrict__ in, __half* __restrict__ out,
                            int R, int C)
{
    __shared__ float t[32][33];
    int c0 = blockIdx.x * 32, r0 = blockIdx.y * 32;
    int x = threadIdx.x, y = threadIdx.y;
#pragma unroll
    for (int j = 0; j < 4; j++)
        t[y + 8 * j][x] = in[(size_t)(r0 + y + 8 * j) * C + c0 + x];
    __syncthreads();
#pragma unroll
    for (int j = 0; j < 4; j++)
        out[(size_t)(c0 + y + 8 * j) * R + r0 + x] = __float2half(t[x][y + 8 * j]);
}

// ---------------------------------------------------------------------------
// fp16 HMMA GEMM: BK=64, XOR-swizzled smem, ldmatrix, 3-stage pipeline.
// ---------------------------------------------------------------------------
#define BK 64
#define TILEB (128 * BK * 2)           // 16384 B per operand tile
#define GEMM_SMEM (6 * TILEB)          // 3 stages x (A,B) = 96 KB

#define GEMM_PRE()                                                            \
    extern __shared__ __half smh[];                                           \
    uint32_t sA = s2u(smh);                                                   \
    uint32_t sB = sA + 3 * TILEB;                                             \
    const int tid = threadIdx.x;                                              \
    const int bn = blockIdx.x * 128;                                          \
    const int bm = blockIdx.y * 128;                                          \
    const int wid = tid >> 5, l = tid & 31;                                   \
    const int wm = (wid & 1) * 64;                                            \
    const int wn = (wid >> 1) * 32;                                           \
    const int nt = K / BK;                                                    \
    const int c2 = (l & 3) * 2;                                               \
    const int lq = l >> 2;                                                    \
    const int ldr = tid >> 3;              /* 0..31 */                        \
    const int ldc8 = tid & 7;              /* chunk col */                    \
    const __half* Ag = A  + (size_t)(bm + ldr) * K + ldc8 * 8;                \
    const __half* Bg = Bt + (size_t)(bn + ldr) * K + ldc8 * 8;                \
    const uint32_t sAo = sA + (ldr * BK + ((ldc8 ^ (ldr & 7)) * 8)) * 2;      \
    const uint32_t sBo = sB + (ldr * BK + ((ldc8 ^ (ldr & 7)) * 8)) * 2;      \
    float acc[4][4][4];                                                       \
    _Pragma("unroll")                                                         \
    for (int i = 0; i < 4; i++)                                               \
        _Pragma("unroll")                                                     \
        for (int j = 0; j < 4; j++)                                           \
            _Pragma("unroll")                                                 \
            for (int c = 0; c < 4; c++) acc[i][j][c] = 0.f;                   \
    const int a_row  = l & 15;                                                \
    const int a_kch  = l >> 4;             /* chunk 0/1 within kk */          \
    const int b_nrow = (l & 7) + ((l >> 4) << 3);                             \
    const int b_kch  = (l >> 3) & 1;

#define LOAD_TILE(T)                                                          \
    {                                                                         \
        int buf_ = (T) % 3;                                                   \
        int ko_ = (T) * BK;                                                   \
        _Pragma("unroll")                                                     \
        for (int p = 0; p < 4; p++) {                                         \
            cpa16(sAo + buf_ * TILEB + p * 32 * BK * 2,                       \
                  Ag + (size_t)(p * 32) * K + ko_);                           \
            cpa16(sBo + buf_ * TILEB + p * 32 * BK * 2,                       \
                  Bg + (size_t)(p * 32) * K + ko_);                           \
        }                                                                     \
        asm volatile("cp.async.commit_group;" ::: "memory");                  \
    }

#define GEMM_MAINLOOP()                                                       \
    LOAD_TILE(0);                                                             \
    if (nt > 1) LOAD_TILE(1);                                                 \
    for (int t = 0; t < nt; t++) {                                            \
        if (t + 1 < nt) { asm volatile("cp.async.wait_group 1;" ::: "memory"); } \
        else            { asm volatile("cp.async.wait_group 0;" ::: "memory"); } \
        __syncthreads();                                                      \
        if (t + 2 < nt) LOAD_TILE(t + 2);                                     \
        uint32_t Ab = sA + (t % 3) * TILEB;                                   \
        uint32_t Bb = sB + (t % 3) * TILEB;                                   \
        _Pragma("unroll")                                                     \
        for (int kk = 0; kk < 4; kk++) {                                      \
            uint32_t a[4][4], bfr[2][4];                                      \
            _Pragma("unroll")                                                 \
            for (int im = 0; im < 4; im++) {                                  \
                int row_ = wm + im * 16 + a_row;                              \
                int ch_ = (kk * 2 + a_kch) ^ (row_ & 7);                      \
                ldsm4(a[im], Ab + (row_ * BK + ch_ * 8) * 2);                 \
            }                                                                 \
            _Pragma("unroll")                                                 \
            for (int g = 0; g < 2; g++) {                                     \
                int row_ = wn + g * 16 + b_nrow;                              \
                int ch_ = (kk * 2 + b_kch) ^ (row_ & 7);                      \
                ldsm4(bfr[g], Bb + (row_ * BK + ch_ * 8) * 2);                \
            }                                                                 \
            _Pragma("unroll")                                                 \
            for (int im = 0; im < 4; im++)                                    \
                _Pragma("unroll")                                             \
                for (int in = 0; in < 4; in++)                                \
                    hmma(acc[im][in], a[im][0], a[im][1], a[im][2], a[im][3], \
                         bfr[in >> 1][(in & 1) * 2], bfr[in >> 1][(in & 1) * 2 + 1]); \
        }                                                                     \
    }

template <int EPI>
__global__ __launch_bounds__(256, 2)
void gemm_mma(const __half* __restrict__ A, const __half* __restrict__ Bt,
              const float* __restrict__ bias, const float* __restrict__ res,
              void* __restrict__ Cv, int N, int K)
{
    GEMM_PRE();
    GEMM_MAINLOOP();

    float*  Cf = (float*)Cv;
    __half* Ch = (__half*)Cv;
#pragma unroll
    for (int im = 0; im < 4; im++) {
        int r0 = bm + wm + im * 16 + lq;
#pragma unroll
        for (int in = 0; in < 4; in++) {
            int cc = bn + wn + in * 8 + c2;
            float b0 = 0.f, b1 = 0.f;
            if (bias) { b0 = bias[cc]; b1 = bias[cc + 1]; }
            float v0 = acc[im][in][0] + b0;
            float v1 = acc[im][in][1] + b1;
            float v2 = acc[im][in][2] + b0;
            float v3 = acc[im][in][3] + b1;
            if (EPI == 1) {
                v0 += res[(size_t)r0 * N + cc];
                v1 += res[(size_t)r0 * N + cc + 1];
                v2 += res[(size_t)(r0 + 8) * N + cc];
                v3 += res[(size_t)(r0 + 8) * N + cc + 1];
            }
            if (EPI == 2 || EPI == 3) {
                if (EPI == 2) {
                    v0 = fmaxf(v0, 0.f); v1 = fmaxf(v1, 0.f);
                    v2 = fmaxf(v2, 0.f); v3 = fmaxf(v3, 0.f);
                }
                *(__half2*)&Ch[(size_t)r0 * N + cc] =
                    __halves2half2(__float2half(v0), __float2half(v1));
                *(__half2*)&Ch[(size_t)(r0 + 8) * N + cc] =
                    __halves2half2(__float2half(v2), __float2half(v3));
            } else {
                *(float2*)&Cf[(size_t)r0 * N + cc] = make_float2(v0, v1);
                *(float2*)&Cf[(size_t)(r0 + 8) * N + cc] = make_float2(v2, v3);
            }
        }
    }
}

// ---------------------------------------------------------------------------
// LM-head GEMM with fused logsumexp partials + target-logit capture.
// ---------------------------------------------------------------------------
__global__ __launch_bounds__(256, 2)
void gemm_lm(const __half* __restrict__ A, const __half* __restrict__ Bt,
             const float* __restrict__ bias, const int* __restrict__ targets,
             float2* __restrict__ part, float* __restrict__ zt, int K)
{
    GEMM_PRE();
    GEMM_MAINLOOP();

#pragma unroll
    for (int im = 0; im < 4; im++) {
        int r0g = bm + wm + im * 16 + lq;
        int r1g = r0g + 8;
        int t0 = targets[r0g], t1 = targets[r1g];
#pragma unroll
        for (int in = 0; in < 4; in++) {
            int cc = bn + wn + in * 8 + c2;
            float b0 = bias[cc], b1 = bias[cc + 1];
            acc[im][in][0] += b0; acc[im][in][1] += b1;
            acc[im][in][2] += b0; acc[im][in][3] += b1;
            if (cc     == t0) zt[r0g] = acc[im][in][0];
            if (cc + 1 == t0) zt[r0g] = acc[im][in][1];
            if (cc     == t1) zt[r1g] = acc[im][in][2];
            if (cc + 1 == t1) zt[r1g] = acc[im][in][3];
        }
    }

    float* redM = (float*)smh;             // [128][4]
    float* redS = redM + 512;
    __syncthreads();

#pragma unroll
    for (int im = 0; im < 4; im++)
#pragma unroll
        for (int h = 0; h < 2; h++) {
            float mx = -INFINITY;
#pragma unroll
            for (int in = 0; in < 4; in++)
                mx = fmaxf(mx, fmaxf(acc[im][in][h * 2], acc[im][in][h * 2 + 1]));
            mx = fmaxf(mx, __shfl_xor_sync(0xFFFFFFFF, mx, 1));
            mx = fmaxf(mx, __shfl_xor_sync(0xFFFFFFFF, mx, 2));
            int row = wm + im * 16 + lq + h * 8;
            if ((l & 3) == 0) redM[row * 4 + (wid >> 1)] = mx;
        }
    __syncthreads();

#pragma unroll
    for (int im = 0; im < 4; im++)
#pragma unroll
        for (int h = 0; h < 2; h++) {
            int row = wm + im * 16 + lq + h * 8;
            float rm = fmaxf(fmaxf(redM[row * 4 + 0], redM[row * 4 + 1]),
                             fmaxf(redM[row * 4 + 2], redM[row * 4 + 3]));
            float se = 0.f;
#pragma unroll
            for (int in = 0; in < 4; in++) {
                float d0 = acc[im][in][h * 2]     - rm;
                float d1 = acc[im][in][h * 2 + 1] - rm;
                if (in & 1) { se += exp_poly(d0); se += exp_poly(d1); }
                else        { se += __expf(d0);   se += __expf(d1);   }
            }
            se += __shfl_xor_sync(0xFFFFFFFF, se, 1);
            se += __shfl_xor_sync(0xFFFFFFFF, se, 2);
            if ((l & 3) == 0) redS[row * 4 + (wid >> 1)] = se;
        }
    __syncthreads();

    if (tid < 128) {
        float m = fmaxf(fmaxf(redM[tid * 4 + 0], redM[tid * 4 + 1]),
                        fmaxf(redM[tid * 4 + 2], redM[tid * 4 + 3]));
        float s = redS[tid * 4 + 0] + redS[tid * 4 + 1]
                + redS[tid * 4 + 2] + redS[tid * 4 + 3];
        part[(size_t)(bm + tid) * NSLAB + blockIdx.x] = make_float2(m, s);
    }
}

// ---------------------------------------------------------------------------
// HMMA attention: 32 q-rows x one (b,h) per CTA. ldmatrix everywhere;
// V consumed via ldmatrix.trans (no smem transpose).
// ---------------------------------------------------------------------------
#define SQ 32
#define SPITCH 1036                    // floats per S row (12 mod 32 -> ldsm conflict-free)
#define KVP 72                         // halves per KV row
#define ATT_SMEM (SQ * SPITCH * 4 + 2 * 128 * KVP * 2 + SQ * KVP * 2)

#define LOAD_KV_TILE(DSTP, GOFF)                                              \
    {                                                                         \
        _Pragma("unroll")                                                     \
        for (int u_ = 0; u_ < 4; u_++) {                                      \
            int c_ = tid + 256 * u_;                                          \
            int tok_ = c_ >> 3, o8_ = (c_ & 7) * 8;                           \
            cpa16(s2u(DSTP) + (tok_ * KVP + o8_) * 2,                         \
                  qkvh + qbase + (GOFF) + (size_t)tok_ * 3072 + o8_);         \
        }                                                                     \
        asm volatile("cp.async.commit_group;" ::: "memory");                  \
    }

__global__ __launch_bounds__(256)
void attn_hmma(const __half* __restrict__ qkvh, float* __restrict__ attn,
               __half* __restrict__ oh)
{
    extern __shared__ float sm[];
    float*  S   = sm;                                  // [32][1036] f32
    __half* KV0 = (__half*)(sm + SQ * SPITCH);         // [128][72]
    __half* KV1 = KV0 + 128 * KVP;
    __half* Q   = KV1 + 128 * KVP;                     // [32][72]

    const int tid = threadIdx.x;
    const int q0 = blockIdx.x * SQ;
    const int bh = blockIdx.y;
    const int b = bh >> 4, hh = bh & 15;
    const int wid = tid >> 5, l = tid & 31;
    const int c2 = (l & 3) * 2;
    const int lq = l >> 2;
    const int l15 = l & 15;
    const int kh8 = (l >> 4) * 8;
    const int bn8 = (l & 7) + ((l >> 4) << 3);
    const int bk8 = ((l >> 3) & 1) * 8;
    const int ntile = (q0 >> 7) + 1;
    const int region = ntile << 7;
    const size_t qbase = (size_t)(b * SEQ) * 3072 + hh * 64;
    const uint32_t Qu = s2u(Q);
    const uint32_t Su = s2u(S);

    {
        int r = tid >> 3, c8 = (tid & 7) * 8;
        cpa16(Qu + (r * KVP + c8) * 2, qkvh + qbase + (size_t)(q0 + r) * 3072 + c8);
    }
    LOAD_KV_TILE(KV0, 1024);

    const int wm = (wid & 1) * 16;
    const int wn = (wid >> 1) * 32;

    // ---- scores ----
    for (int t = 0; t < ntile; t++) {
        if (t + 1 < ntile) {
            __half* KB = ((t + 1) & 1) ? KV1 : KV0;
            size_t goff = 1024 + (size_t)((t + 1) << 7) * 3072;
            LOAD_KV_TILE(KB, goff);
            asm volatile("cp.async.wait_group 1;" ::: "memory");
        } else {
            asm volatile("cp.async.wait_group 0;" ::: "memory");
        }
        __syncthreads();
        const uint32_t kbu = s2u((t & 1) ? KV1 : KV0);
        int kt0 = t << 7;
        float acc[4][4];
#pragma unroll
        for (int in = 0; in < 4; in++)
#pragma unroll
            for (int c = 0; c < 4; c++) acc[in][c] = 0.f;
#pragma unroll
        for (int kk = 0; kk < 4; kk++) {
            int k0 = kk * 16;
            uint32_t qa[4], kb0[4], kb1[4];
            ldsm4(qa,  Qu  + ((wm + l15) * KVP + k0 + kh8) * 2);
            ldsm4(kb0, kbu + ((wn + bn8) * KVP + k0 + bk8) * 2);
            ldsm4(kb1, kbu + ((wn + 16 + bn8) * KVP + k0 + bk8) * 2);
            hmma(acc[0], qa[0], qa[1], qa[2], qa[3], kb0[0], kb0[1]);
            hmma(acc[1], qa[0], qa[1], qa[2], qa[3], kb0[2], kb0[3]);
            hmma(acc[2], qa[0], qa[1], qa[2], qa[3], kb1[0], kb1[1]);
            hmma(acc[3], qa[0], qa[1], qa[2], qa[3], kb1[2], kb1[3]);
        }
        int qr = wm + lq;
#pragma unroll
        for (int in = 0; in < 4; in++) {
            int kg = kt0 + wn + in * 8 + c2;
            float v0 = (kg     <= q0 + qr)     ? acc[in][0] * 0.125f : -INFINITY;
            float v1 = (kg + 1 <= q0 + qr)     ? acc[in][1] * 0.125f : -INFINITY;
            float v2 = (kg     <= q0 + qr + 8) ? acc[in][2] * 0.125f : -INFINITY;
            float v3 = (kg + 1 <= q0 + qr + 8) ? acc[in][3] * 0.125f : -INFINITY;
            *(float2*)&S[qr * SPITCH + kg]       = make_float2(v0, v1);
            *(float2*)&S[(qr + 8) * SPITCH + kg] = make_float2(v2, v3);
        }
        __syncthreads();
    }

    // prefetch V tile 0 (overlaps softmax)
    LOAD_KV_TILE(KV0, 2048);

    // ---- softmax ----
    for (int rr = 0; rr < 4; rr++) {
        int q = wid * 4 + rr;
        int qt = q0 + q;
        float* Sr = S + q * SPITCH;
        float m = -INFINITY;
        for (int j = l; j <= qt; j += 32) m = fmaxf(m, Sr[j]);
#pragma unroll
        for (int st = 16; st > 0; st >>= 1)
            m = fmaxf(m, __shfl_xor_sync(0xFFFFFFFF, m, st));
        float ssum = 0.f;
        int it = 0;
        for (int j = l; j <= qt; j += 32, it++) {
            float d = Sr[j] - m;
            float e = (it & 1) ? exp_poly(d) : __expf(d);
            Sr[j] = e;
            ssum += e;
        }
#pragma unroll
        for (int st = 16; st > 0; st >>= 1)
            ssum += __shfl_xor_sync(0xFFFFFFFF, ssum, st);
        float inv = 1.0f / ssum;
        __half* Pr = (__half*)Sr;
        float* dst = attn + ((size_t)bh * SEQ + qt) * SEQ;
        for (int j = l; j < region; j += 32) {
            float p = (j <= qt) ? Sr[j] * inv : 0.f;
            dst[j] = p;
            Pr[j] = __float2half(p);
        }
        for (int j = region + l; j < SEQ; j += 32) dst[j] = 0.f;
    }
    __syncthreads();

    // ---- AV: P (A frags via ldsm on S-as-half) x V (B frags via ldsm.trans) ----
    const int wn2 = (wid >> 1) * 16;
    float oacc[2][4];
#pragma unroll
    for (int in = 0; in < 2; in++)
#pragma unroll
        for (int c = 0; c < 4; c++) oacc[in][c] = 0.f;

    for (int t = 0; t < ntile; t++) {
        if (t + 1 < ntile) {
            __half* KB = ((t + 1) & 1) ? KV1 : KV0;
            size_t goff = 2048 + (size_t)((t + 1) << 7) * 3072;
            LOAD_KV_TILE(KB, goff);
            asm volatile("cp.async.wait_group 1;" ::: "memory");
        } else {
            asm volatile("cp.async.wait_group 0;" ::: "memory");
        }
        __syncthreads();
        const uint32_t kbu = s2u((t & 1) ? KV1 : KV0);
        int kt0 = t << 7;
#pragma unroll
        for (int kk = 0; kk < 8; kk++) {
            int k0 = kk * 16;
            uint32_t pa[4], vb[4];
            ldsm4(pa, Su + ((wm + l15) * (SPITCH * 2) + kt0 + k0 + kh8) * 2);
            ldsm4t(vb, kbu + ((k0 + l15) * KVP + wn2 + kh8) * 2);
            hmma(oacc[0], pa[0], pa[1], pa[2], pa[3], vb[0], vb[1]);
            hmma(oacc[1], pa[0], pa[1], pa[2], pa[3], vb[2], vb[3]);
        }
        __syncthreads();
    }
#pragma unroll
    for (int in = 0; in < 2; in++) {
        int q = q0 + wm + lq;
        int s = wn2 + in * 8 + c2;
        *(__half2*)&oh[(size_t)(b * SEQ + q) * DIM + hh * 64 + s] =
            __halves2half2(__float2half(oacc[in][0]), __float2half(oacc[in][1]));
        *(__half2*)&oh[(size_t)(b * SEQ + q + 8) * DIM + hh * 64 + s] =
            __halves2half2(__float2half(oacc[in][2]), __float2half(oacc[in][3]));
    }
}
#undef LOAD_KV_TILE

// ---------------------------------------------------------------------------
// Merge per-slab (m,s) partials -> per-row loss
// ---------------------------------------------------------------------------
__global__ __launch_bounds__(256)
void loss_from_parts(const float2* __restrict__ part, const float* __restrict__ zt,
                     float* __restrict__ rowloss)
{
    int w = threadIdx.x >> 5, l = threadIdx.x & 31;
    int row = blockIdx.x * 8 + w;
    float m = -INFINITY, s = 0.f;
    for (int p = l; p < NSLAB; p += 32) {
        float2 ps = part[(size_t)row * NSLAB + p];
        float M = fmaxf(m, ps.x);
        s = s * __expf(m - M) + ps.y * __expf(ps.x - M);
        m = M;
    }
#pragma unroll
    for (int st = 16; st > 0; st >>= 1) {
        float m2 = __shfl_xor_sync(0xFFFFFFFF, m, st);
        float s2 = __shfl_xor_sync(0xFFFFFFFF, s, st);
        float M = fmaxf(m, m2);
        s = s * __expf(m - M) + s2 * __expf(m2 - M);
        m = M;
    }
    if (l == 0) rowloss[row] = m + logf(s) - zt[row];
}

__global__ void loss_reduce_kernel(const float* __restrict__ rowloss, float* __restrict__ out)
{
    __shared__ float red[256];
    int tid = threadIdx.x;
    float s = 0.f;
    for (int i = tid; i < ROWS; i += 256) s += rowloss[i];
    red[tid] = s;
    __syncthreads();
    for (int st = 128; st > 0; st >>= 1) {
        if (tid < st) red[tid] += red[tid + st];
        __syncthreads();
    }
    if (tid == 0) out[0] = red[0] * (1.0f / ROWS);
}

// ---------------------------------------------------------------------------
// Host
// ---------------------------------------------------------------------------
extern "C" void kernel_launch(void* const* d_in, const int* in_sizes, int n_in,
                              void* d_out, int out_size)
{
    const int*   idx     = (const int*)  d_in[0];
    const int*   targets = (const int*)  d_in[1];
    const float* tok_emb = (const float*)d_in[2];
    const float* pos_emb = (const float*)d_in[3];
    const float* ln1_g   = (const float*)d_in[4];
    const float* ln1_b   = (const float*)d_in[5];
    const float* Wq      = (const float*)d_in[6];
    const float* Wk      = (const float*)d_in[7];
    const float* Wv      = (const float*)d_in[8];
    const float* Wp      = (const float*)d_in[9];
    const float* bp      = (const float*)d_in[10];
    const float* ln2_g   = (const float*)d_in[11];
    const float* ln2_b   = (const float*)d_in[12];
    const float* W1      = (const float*)d_in[13];
    const float* b1      = (const float*)d_in[14];
    const float* W2      = (const float*)d_in[15];
    const float* b2      = (const float*)d_in[16];
    const float* lnf_g   = (const float*)d_in[17];
    const float* lnf_b   = (const float*)d_in[18];
    const float* Wlm     = (const float*)d_in[19];
    const float* blm     = (const float*)d_in[20];

    float* out      = (float*)d_out;
    float* attn_out = out + 1;

    float *x, *rl, *ztp;
    float2* part;
    __half *hbuf, *qkvh, *ohb, *ffh, *wth;
    cudaGetSymbolAddress((void**)&x,    g_x);
    cudaGetSymbolAddress((void**)&hbuf, g_hh);
    cudaGetSymbolAddress((void**)&qkvh, g_qkvh);
    cudaGetSymbolAddress((void**)&ohb,  g_oh);
    cudaGetSymbolAddress((void**)&ffh,  g_ffh);
    cudaGetSymbolAddress((void**)&wth,  g_wth);
    cudaGetSymbolAddress((void**)&part, g_part);
    cudaGetSymbolAddress((void**)&ztp,  g_zt);
    cudaGetSymbolAddress((void**)&rl,   g_rl);

    cudaFuncSetAttribute(gemm_mma<0>, cudaFuncAttributeMaxDynamicSharedMemorySize, GEMM_SMEM);
    cudaFuncSetAttribute(gemm_mma<1>, cudaFuncAttributeMaxDynamicSharedMemorySize, GEMM_SMEM);
    cudaFuncSetAttribute(gemm_mma<2>, cudaFuncAttributeMaxDynamicSharedMemorySize, GEMM_SMEM);
    cudaFuncSetAttribute(gemm_mma<3>, cudaFuncAttributeMaxDynamicSharedMemorySize, GEMM_SMEM);
    cudaFuncSetAttribute(gemm_lm,     cudaFuncAttributeMaxDynamicSharedMemorySize, GEMM_SMEM);
    cudaFuncSetAttribute(attn_hmma,   cudaFuncAttributeMaxDynamicSharedMemorySize, ATT_SMEM);

    embed_kernel<<<ROWS, 256>>>(idx, tok_emb, pos_emb, x);

    for (int l = 0; l < NL; l++) {
        ln_kernel<<<ROWS / 8, 256>>>(x, ln1_g + (size_t)l * DIM, ln1_b + (size_t)l * DIM, hbuf);
        pack_qkv_t<<<dim3(HS / 32, DIM / 32, 3 * NH), dim3(32, 8)>>>(Wq, Wk, Wv, wth, l);
        gemm_mma<3><<<dim3(3 * DIM / 128, ROWS / 128), 256, GEMM_SMEM>>>(
            hbuf, wth, nullptr, nullptr, qkvh, 3 * DIM, DIM);

        float* attnL = attn_out + (size_t)l * BATCH * NH * SEQ * SEQ;
        attn_hmma<<<dim3(SEQ / SQ, BATCH * NH), 256, ATT_SMEM>>>(qkvh, attnL, ohb);

        transpose_k<<<dim3(DIM / 32, DIM / 32), dim3(32, 8)>>>(
            Wp + (size_t)l * DIM * DIM, wth, DIM, DIM);
        gemm_mma<1><<<dim3(DIM / 128, ROWS / 128), 256, GEMM_SMEM>>>(
            ohb, wth, bp + (size_t)l * DIM, x, x, DIM, DIM);

        ln_kernel<<<ROWS / 8, 256>>>(x, ln2_g + (size_t)l * DIM, ln2_b + (size_t)l * DIM, hbuf);

        transpose_k<<<dim3(FFD / 32, DIM / 32), dim3(32, 8)>>>(
            W1 + (size_t)l * DIM * FFD, wth, DIM, FFD);
        gemm_mma<2><<<dim3(FFD / 128, ROWS / 128), 256, GEMM_SMEM>>>(
            hbuf, wth, b1 + (size_t)l * FFD, nullptr, ffh, FFD, DIM);

        transpose_k<<<dim3(DIM / 32, FFD / 32), dim3(32, 8)>>>(
            W2 + (size_t)l * FFD * DIM, wth, FFD, DIM);
        gemm_mma<1><<<dim3(DIM / 128, ROWS / 128), 256, GEMM_SMEM>>>(
            ffh, wth, b2 + (size_t)l * DIM, x, x, DIM, FFD);
    }

    ln_kernel<<<ROWS / 8, 256>>>(x, lnf_g, lnf_b, hbuf);
    transpose_k<<<dim3(VOCAB / 32, DIM / 32), dim3(32, 8)>>>(Wlm, wth, DIM, VOCAB);
    gemm_lm<<<dim3(NSLAB, ROWS / 128), 256, GEMM_SMEM>>>(
        hbuf, wth, blm, targets, part, ztp, DIM);

    loss_from_parts<<<ROWS / 8, 256>>>(part, ztp, rl);
    loss_reduce_kernel<<<1, 256>>>(rl, out);
}